// round 1
// baseline (speedup 1.0000x reference)
#include <cuda_runtime.h>
#include <math.h>

#define SEQ     1024
#define D_MODEL 1024
#define NHEADS  16
#define DHEAD   64
#define HIDDEN  4096
#define NBATCH  2
#define ROWS    (NBATCH*SEQ)   // 2048

#define BM 128
#define BN 64
#define BK 8

// ---------------- scratch (device statics; no allocation) ----------------
__device__ float g_Qr[ROWS*D_MODEL];
__device__ float g_Qi[ROWS*D_MODEL];
__device__ float g_Kr[ROWS*D_MODEL];
__device__ float g_Ki[ROWS*D_MODEL];
__device__ float g_Vr[ROWS*D_MODEL];
__device__ float g_Vi[ROWS*D_MODEL];
__device__ float g_Xr[ROWS*D_MODEL];
__device__ float g_Xi[ROWS*D_MODEL];
__device__ float g_Or[ROWS*D_MODEL];
__device__ float g_Oi[ROWS*D_MODEL];
__device__ float g_Hr[ROWS*HIDDEN];
__device__ float g_Hi[ROWS*HIDDEN];
__device__ float g_Sc[NBATCH*NHEADS*SEQ*SEQ];   // 128 MB scores/attn
__device__ float g_M [D_MODEL*D_MODEL];
__device__ float g_Ta[D_MODEL*D_MODEL];
__device__ float g_Tb[D_MODEL*D_MODEL];
__device__ float g_Ur[D_MODEL*D_MODEL];
__device__ float g_Ui[D_MODEL*D_MODEL];

// ---------------- generic strided-batched fp32 GEMM ----------------
// C[m,n] = (acc ? C[m,n] : 0) + alpha * sum_k A[m*sAm + k*sAk] * B[n*sBn + k*sBk]
// batch offsets: z -> (z/batchDiv)*X1 + (z%batchDiv)*X2
__global__ __launch_bounds__(256) void gemm_kernel(
    float* __restrict__ C, const float* __restrict__ A, const float* __restrict__ B,
    int M, int N, int K,
    long long sAm, long long sAk, long long sBn, long long sBk, long long sCm,
    long long aB1, long long aB2, long long bB1, long long bB2,
    long long cB1, long long cB2, int batchDiv,
    float alpha, int accumulate)
{
    __shared__ float As[BK][BM+4];
    __shared__ float Bs[BK][BN+4];
    int z = blockIdx.z;
    int zb = z / batchDiv, zh = z % batchDiv;
    A += (long long)zb*aB1 + (long long)zh*aB2;
    B += (long long)zb*bB1 + (long long)zh*bB2;
    C += (long long)zb*cB1 + (long long)zh*cB2;
    int m0 = blockIdx.y*BM, n0 = blockIdx.x*BN;
    int tid = threadIdx.x;
    int tm = tid >> 4, tn = tid & 15;

    float acc[8][4];
    #pragma unroll
    for (int i = 0; i < 8; i++)
        #pragma unroll
        for (int j = 0; j < 4; j++) acc[i][j] = 0.f;

    for (int k0 = 0; k0 < K; k0 += BK) {
        #pragma unroll
        for (int i = 0; i < 4; i++) {
            int idx = tid + i*256;
            int m = idx >> 3, k = idx & 7;
            int gm = m0 + m, gk = k0 + k;
            float v = 0.f;
            if (gm < M && gk < K) v = A[(long long)gm*sAm + (long long)gk*sAk];
            As[k][m] = v;
        }
        #pragma unroll
        for (int i = 0; i < 2; i++) {
            int idx = tid + i*256;
            int n = idx >> 3, k = idx & 7;
            int gn = n0 + n, gk = k0 + k;
            float v = 0.f;
            if (gn < N && gk < K) v = B[(long long)gn*sBn + (long long)gk*sBk];
            Bs[k][n] = v;
        }
        __syncthreads();
        #pragma unroll
        for (int k = 0; k < BK; k++) {
            float4 a0 = *(const float4*)&As[k][tm*8];
            float4 a1 = *(const float4*)&As[k][tm*8+4];
            float4 b0 = *(const float4*)&Bs[k][tn*4];
            float a[8] = {a0.x,a0.y,a0.z,a0.w,a1.x,a1.y,a1.z,a1.w};
            float b[4] = {b0.x,b0.y,b0.z,b0.w};
            #pragma unroll
            for (int i = 0; i < 8; i++)
                #pragma unroll
                for (int j = 0; j < 4; j++)
                    acc[i][j] += a[i]*b[j];
        }
        __syncthreads();
    }
    #pragma unroll
    for (int i = 0; i < 8; i++) {
        int gm = m0 + tm*8 + i;
        if (gm >= M) continue;
        #pragma unroll
        for (int j = 0; j < 4; j++) {
            int gn = n0 + tn*4 + j;
            if (gn >= N) continue;
            long long p = (long long)gm*sCm + gn;
            float v = alpha*acc[i][j];
            if (accumulate) v += C[p];
            C[p] = v;
        }
    }
}

// ---------------- 1024-pt complex FFT (radix-2 Stockham), one block/column ----
// layout: element n of column (b, c) at base + n*D_MODEL, base = b*SEQ*D_MODEL + c
__global__ __launch_bounds__(512) void fft_kernel(float* __restrict__ re,
                                                  float* __restrict__ im,
                                                  int inverse)
{
    __shared__ float sr[2][1024];
    __shared__ float si[2][1024];
    int col = blockIdx.x;
    int b   = col >> 10;
    int rem = col & 1023;
    long long base = (long long)b * SEQ * D_MODEL + rem;
    int t = threadIdx.x;

    sr[0][t]      = re[base + (long long)t*D_MODEL];
    si[0][t]      = im[base + (long long)t*D_MODEL];
    sr[0][t+512]  = re[base + (long long)(t+512)*D_MODEL];
    si[0][t+512]  = im[base + (long long)(t+512)*D_MODEL];
    __syncthreads();

    float sgn = inverse ? 6.283185307179586f : -6.283185307179586f;
    int cur = 0;
    #pragma unroll
    for (int s = 0; s < 10; s++) {
        int L = 1 << s;
        int l = t & (L-1);
        int r = t >> s;
        float ar = sr[cur][t],     ai = si[cur][t];
        float br = sr[cur][t+512], bi = si[cur][t+512];
        float ang = sgn * (float)l / (float)(2*L);
        float c, sn;
        sincosf(ang, &sn, &c);
        float tr = c*br - sn*bi;
        float ti = c*bi + sn*br;
        int nxt = cur ^ 1;
        int o = r*(2*L) + l;
        sr[nxt][o]   = ar + tr;  si[nxt][o]   = ai + ti;
        sr[nxt][o+L] = ar - tr;  si[nxt][o+L] = ai - ti;
        cur = nxt;
        __syncthreads();
    }
    float sc = inverse ? (1.0f/1024.0f) : 1.0f;
    re[base + (long long)t*D_MODEL]       = sr[cur][t]*sc;
    im[base + (long long)t*D_MODEL]       = si[cur][t]*sc;
    re[base + (long long)(t+512)*D_MODEL] = sr[cur][t+512]*sc;
    im[base + (long long)(t+512)*D_MODEL] = si[cur][t+512]*sc;
}

// ---------------- row softmax over 1024 columns ----------------
__global__ __launch_bounds__(256) void softmax_kernel(float* __restrict__ S)
{
    long long row = blockIdx.x;
    float* p = S + row*1024;
    int t = threadIdx.x;
    __shared__ float red[256];

    float m = -1e30f;
    #pragma unroll
    for (int i = 0; i < 4; i++) m = fmaxf(m, p[t + i*256]);
    red[t] = m; __syncthreads();
    for (int s = 128; s > 0; s >>= 1) { if (t < s) red[t] = fmaxf(red[t], red[t+s]); __syncthreads(); }
    m = red[0]; __syncthreads();

    float vals[4]; float sum = 0.f;
    #pragma unroll
    for (int i = 0; i < 4; i++) { vals[i] = expf(p[t + i*256] - m); sum += vals[i]; }
    red[t] = sum; __syncthreads();
    for (int s = 128; s > 0; s >>= 1) { if (t < s) red[t] += red[t+s]; __syncthreads(); }
    float inv = 1.0f / red[0];
    #pragma unroll
    for (int i = 0; i < 4; i++) p[t + i*256] = vals[i]*inv;
}

// ---------------- elementwise helpers ----------------
__global__ void epilogue_kernel(float* __restrict__ Y, const float* __restrict__ bias,
                                long long total, int Ncols, int gelu)
{
    long long i = (long long)blockIdx.x*blockDim.x + threadIdx.x;
    if (i >= total) return;
    int n = (int)(i % Ncols);
    float v = Y[i] + bias[n];
    if (gelu) v = 0.5f * v * (1.0f + erff(v * 0.7071067811865476f));
    Y[i] = v;
}
__global__ void copy_kernel(float* __restrict__ y, const float* __restrict__ x, long long n)
{
    long long i = (long long)blockIdx.x*blockDim.x + threadIdx.x;
    if (i < n) y[i] = x[i];
}
__global__ void scale_kernel(float* __restrict__ y, const float* __restrict__ x,
                             const float* __restrict__ dt, long long n)
{
    long long i = (long long)blockIdx.x*blockDim.x + threadIdx.x;
    if (i < n) y[i] = x[i]*dt[0];
}
__global__ void initU_kernel(float* __restrict__ Ur, float* __restrict__ Ui)
{
    long long i = (long long)blockIdx.x*blockDim.x + threadIdx.x;
    if (i < (long long)D_MODEL*D_MODEL) {
        Ur[i] = ((i / D_MODEL) == (i % D_MODEL)) ? 1.f : 0.f;
        Ui[i] = 0.f;
    }
}
__global__ void axpy_kernel(float* __restrict__ y, const float* __restrict__ x,
                            float c, long long n)
{
    long long i = (long long)blockIdx.x*blockDim.x + threadIdx.x;
    if (i < n) y[i] += c*x[i];
}

// ---------------- host orchestration ----------------
static void launch_gemm(float* C, const float* A, const float* B,
    int M, int N, int K,
    long long sAm, long long sAk, long long sBn, long long sBk, long long sCm,
    float alpha, int acc,
    int batch = 1, int batchDiv = 1,
    long long aB1 = 0, long long aB2 = 0,
    long long bB1 = 0, long long bB2 = 0,
    long long cB1 = 0, long long cB2 = 0)
{
    dim3 grid((N+BN-1)/BN, (M+BM-1)/BM, batch);
    gemm_kernel<<<grid, 256>>>(C, A, B, M, N, K, sAm, sAk, sBn, sBk, sCm,
                               aB1, aB2, bB1, bB2, cB1, cB2, batchDiv, alpha, acc);
}

static void launch_epilogue(float* Y, const float* bias, long long rows, int ncols, int gelu)
{
    long long total = rows*(long long)ncols;
    int blocks = (int)((total + 255)/256);
    epilogue_kernel<<<blocks, 256>>>(Y, bias, total, ncols, gelu);
}

// complex linear: (Yr,Yi) = (Xr,Xi) @ (Wr,Wi)^T + (br,bi); optional gelu; optional accumulate
static void clin(float* Yr, float* Yi,
                 const float* Xr, const float* Xi,
                 const float* Wr, const float* Wi,
                 const float* br, const float* bi,
                 int M, int N, int K, int acc, int gelu)
{
    // Yr (+)= Xr*Wr^T - Xi*Wi^T ; Yi (+)= Xr*Wi^T + Xi*Wr^T
    launch_gemm(Yr, Xr, Wr, M, N, K, K, 1, K, 1, N,  1.f, acc);
    launch_gemm(Yr, Xi, Wi, M, N, K, K, 1, K, 1, N, -1.f, 1);
    launch_gemm(Yi, Xr, Wi, M, N, K, K, 1, K, 1, N,  1.f, acc);
    launch_gemm(Yi, Xi, Wr, M, N, K, K, 1, K, 1, N,  1.f, 1);
    launch_epilogue(Yr, br, M, N, gelu);
    launch_epilogue(Yi, bi, M, N, gelu);
}

extern "C" void kernel_launch(void* const* d_in, const int* in_sizes, int n_in,
                              void* d_out, int out_size)
{
    const float* x_real = (const float*)d_in[0];
    const float* x_imag = (const float*)d_in[1];
    const float* Wr_q = (const float*)d_in[2];   const float* Wi_q = (const float*)d_in[3];
    const float* br_q = (const float*)d_in[4];   const float* bi_q = (const float*)d_in[5];
    const float* Wr_k = (const float*)d_in[6];   const float* Wi_k = (const float*)d_in[7];
    const float* br_k = (const float*)d_in[8];   const float* bi_k = (const float*)d_in[9];
    const float* Wr_v = (const float*)d_in[10];  const float* Wi_v = (const float*)d_in[11];
    const float* br_v = (const float*)d_in[12];  const float* bi_v = (const float*)d_in[13];
    const float* Wr_o = (const float*)d_in[14];  const float* Wi_o = (const float*)d_in[15];
    const float* br_o = (const float*)d_in[16];  const float* bi_o = (const float*)d_in[17];
    const float* Wr_f1 = (const float*)d_in[18]; const float* Wi_f1 = (const float*)d_in[19];
    const float* br_f1 = (const float*)d_in[20]; const float* bi_f1 = (const float*)d_in[21];
    const float* Wr_f2 = (const float*)d_in[22]; const float* Wi_f2 = (const float*)d_in[23];
    const float* br_f2 = (const float*)d_in[24]; const float* bi_f2 = (const float*)d_in[25];
    const float* Hmat = (const float*)d_in[26];
    const float* dtp  = (const float*)d_in[27];

    float* outRe = (float*)d_out;
    float* outIm = outRe + (long long)ROWS*D_MODEL;

    float *Qr,*Qi,*Kr,*Ki,*Vr,*Vi,*Xr,*Xi,*Or,*Oi,*Hr,*Hi,*Sc,*Mb,*Ta,*Tb,*Ur,*Ui;
    cudaGetSymbolAddress((void**)&Qr, g_Qr); cudaGetSymbolAddress((void**)&Qi, g_Qi);
    cudaGetSymbolAddress((void**)&Kr, g_Kr); cudaGetSymbolAddress((void**)&Ki, g_Ki);
    cudaGetSymbolAddress((void**)&Vr, g_Vr); cudaGetSymbolAddress((void**)&Vi, g_Vi);
    cudaGetSymbolAddress((void**)&Xr, g_Xr); cudaGetSymbolAddress((void**)&Xi, g_Xi);
    cudaGetSymbolAddress((void**)&Or, g_Or); cudaGetSymbolAddress((void**)&Oi, g_Oi);
    cudaGetSymbolAddress((void**)&Hr, g_Hr); cudaGetSymbolAddress((void**)&Hi, g_Hi);
    cudaGetSymbolAddress((void**)&Sc, g_Sc);
    cudaGetSymbolAddress((void**)&Mb, g_M);  cudaGetSymbolAddress((void**)&Ta, g_Ta);
    cudaGetSymbolAddress((void**)&Tb, g_Tb);
    cudaGetSymbolAddress((void**)&Ur, g_Ur); cudaGetSymbolAddress((void**)&Ui, g_Ui);

    const long long ND = (long long)ROWS*D_MODEL;
    copy_kernel<<<(int)((ND+255)/256), 256>>>(Xr, x_real, ND);
    copy_kernel<<<(int)((ND+255)/256), 256>>>(Xi, x_imag, ND);

    // ---- Q/K/V projections (from original x) ----
    clin(Qr, Qi, Xr, Xi, Wr_q, Wi_q, br_q, bi_q, ROWS, D_MODEL, D_MODEL, 0, 0);
    clin(Kr, Ki, Xr, Xi, Wr_k, Wi_k, br_k, bi_k, ROWS, D_MODEL, D_MODEL, 0, 0);
    clin(Vr, Vi, Xr, Xi, Wr_v, Wi_v, br_v, bi_v, ROWS, D_MODEL, D_MODEL, 0, 0);

    // ---- forward FFT along sequence axis (per b, per channel) ----
    fft_kernel<<<NBATCH*D_MODEL, 512>>>(Qr, Qi, 0);
    fft_kernel<<<NBATCH*D_MODEL, 512>>>(Kr, Ki, 0);
    fft_kernel<<<NBATCH*D_MODEL, 512>>>(Vr, Vi, 0);

    // ---- scores.real = scale*(Qfr Kfr^T + Qfi Kfi^T), batched over (b,h) ----
    {
        const float scale = 0.125f; // 1/sqrt(64)
        long long hM = (long long)SEQ*SEQ;                  // per-head score block
        launch_gemm(Sc, Qr, Kr, SEQ, SEQ, DHEAD,
                    D_MODEL, 1, D_MODEL, 1, SEQ, scale, 0,
                    NBATCH*NHEADS, NHEADS,
                    (long long)SEQ*D_MODEL, DHEAD,
                    (long long)SEQ*D_MODEL, DHEAD,
                    (long long)NHEADS*hM, hM);
        launch_gemm(Sc, Qi, Ki, SEQ, SEQ, DHEAD,
                    D_MODEL, 1, D_MODEL, 1, SEQ, scale, 1,
                    NBATCH*NHEADS, NHEADS,
                    (long long)SEQ*D_MODEL, DHEAD,
                    (long long)SEQ*D_MODEL, DHEAD,
                    (long long)NHEADS*hM, hM);
    }

    softmax_kernel<<<NBATCH*NHEADS*SEQ, 256>>>(Sc);

    // ---- out_f = attn @ Vf (attn real) ----
    {
        long long hM = (long long)SEQ*SEQ;
        launch_gemm(Or, Sc, Vr, SEQ, DHEAD, SEQ,
                    SEQ, 1, 1, D_MODEL, D_MODEL, 1.f, 0,
                    NBATCH*NHEADS, NHEADS,
                    (long long)NHEADS*hM, hM,
                    (long long)SEQ*D_MODEL, DHEAD,
                    (long long)SEQ*D_MODEL, DHEAD);
        launch_gemm(Oi, Sc, Vi, SEQ, DHEAD, SEQ,
                    SEQ, 1, 1, D_MODEL, D_MODEL, 1.f, 0,
                    NBATCH*NHEADS, NHEADS,
                    (long long)NHEADS*hM, hM,
                    (long long)SEQ*D_MODEL, DHEAD,
                    (long long)SEQ*D_MODEL, DHEAD);
    }

    // ---- inverse FFT ----
    fft_kernel<<<NBATCH*D_MODEL, 512>>>(Or, Oi, 1);

    // ---- x += clin(out, Wo) ----
    launch_gemm(Xr, Or, Wr_o, ROWS, D_MODEL, D_MODEL, D_MODEL, 1, D_MODEL, 1, D_MODEL,  1.f, 1);
    launch_gemm(Xr, Oi, Wi_o, ROWS, D_MODEL, D_MODEL, D_MODEL, 1, D_MODEL, 1, D_MODEL, -1.f, 1);
    launch_gemm(Xi, Or, Wi_o, ROWS, D_MODEL, D_MODEL, D_MODEL, 1, D_MODEL, 1, D_MODEL,  1.f, 1);
    launch_gemm(Xi, Oi, Wr_o, ROWS, D_MODEL, D_MODEL, D_MODEL, 1, D_MODEL, 1, D_MODEL,  1.f, 1);
    launch_epilogue(Xr, br_o, ROWS, D_MODEL, 0);
    launch_epilogue(Xi, bi_o, ROWS, D_MODEL, 0);

    // ---- FFN: h = gelu(clin(x, Wf1)); x += clin(h, Wf2) ----
    clin(Hr, Hi, Xr, Xi, Wr_f1, Wi_f1, br_f1, bi_f1, ROWS, HIDDEN, D_MODEL, 0, 1);
    launch_gemm(Xr, Hr, Wr_f2, ROWS, D_MODEL, HIDDEN, HIDDEN, 1, HIDDEN, 1, D_MODEL,  1.f, 1);
    launch_gemm(Xr, Hi, Wi_f2, ROWS, D_MODEL, HIDDEN, HIDDEN, 1, HIDDEN, 1, D_MODEL, -1.f, 1);
    launch_gemm(Xi, Hr, Wi_f2, ROWS, D_MODEL, HIDDEN, HIDDEN, 1, HIDDEN, 1, D_MODEL,  1.f, 1);
    launch_gemm(Xi, Hi, Wr_f2, ROWS, D_MODEL, HIDDEN, HIDDEN, 1, HIDDEN, 1, D_MODEL,  1.f, 1);
    launch_epilogue(Xr, br_f2, ROWS, D_MODEL, 0);
    launch_epilogue(Xi, bi_f2, ROWS, D_MODEL, 0);

    // ---- U = expm(-i H dt) via Taylor (||H dt|| ~ 0.05): U = Ur + i Ui ----
    const long long DD = (long long)D_MODEL*D_MODEL;
    scale_kernel<<<(int)((DD+255)/256), 256>>>(Mb, Hmat, dtp, DD);
    initU_kernel<<<(int)((DD+255)/256), 256>>>(Ur, Ui);
    // k=1: (-i)^1/1! = -i
    axpy_kernel<<<(int)((DD+255)/256), 256>>>(Ui, Mb, -1.0f, DD);
    {
        // powers: M^k symmetric -> NT form with B = M works throughout
        float* prev = Mb;
        float* bufs[2] = { Ta, Tb };
        // k, target(0=Ur,1=Ui), coefficient of M^k
        const int   tgt [5] = { 0, 1, 0, 1, 0 };
        const float coef[5] = { -0.5f, 1.0f/6.0f, 1.0f/24.0f, -1.0f/120.0f, -1.0f/720.0f };
        for (int s = 0; s < 5; s++) {
            float* dst = bufs[s & 1];
            launch_gemm(dst, prev, Mb, D_MODEL, D_MODEL, D_MODEL,
                        D_MODEL, 1, D_MODEL, 1, D_MODEL, 1.f, 0);
            axpy_kernel<<<(int)((DD+255)/256), 256>>>(tgt[s] ? Ui : Ur, dst, coef[s], DD);
            prev = dst;
        }
    }

    // ---- out = x @ U (U symmetric => NT form with B = U) ----
    launch_gemm(outRe, Xr, Ur, ROWS, D_MODEL, D_MODEL, D_MODEL, 1, D_MODEL, 1, D_MODEL,  1.f, 0);
    launch_gemm(outRe, Xi, Ui, ROWS, D_MODEL, D_MODEL, D_MODEL, 1, D_MODEL, 1, D_MODEL, -1.f, 1);
    launch_gemm(outIm, Xr, Ui, ROWS, D_MODEL, D_MODEL, D_MODEL, 1, D_MODEL, 1, D_MODEL,  1.f, 0);
    launch_gemm(outIm, Xi, Ur, ROWS, D_MODEL, D_MODEL, D_MODEL, 1, D_MODEL, 1, D_MODEL,  1.f, 1);
}

// round 2
// speedup vs baseline: 1.3745x; 1.3745x over previous
#include <cuda_runtime.h>
#include <math.h>
#include <stdint.h>

#define SEQ     1024
#define D_MODEL 1024
#define NHEADS  16
#define DHEAD   64
#define HIDDEN  4096
#define NBATCH  2
#define ROWS    (NBATCH*SEQ)   // 2048

// ---------------- scratch (device statics; no allocation) ----------------
__device__ float g_Qr[ROWS*D_MODEL];
__device__ float g_Qi[ROWS*D_MODEL];
__device__ float g_Kr[ROWS*D_MODEL];
__device__ float g_Ki[ROWS*D_MODEL];
__device__ float g_Vr[ROWS*D_MODEL];
__device__ float g_Vi[ROWS*D_MODEL];
__device__ float g_Xr[ROWS*D_MODEL];
__device__ float g_Xi[ROWS*D_MODEL];
__device__ float g_Or[ROWS*D_MODEL];
__device__ float g_Oi[ROWS*D_MODEL];
__device__ float g_Hr[ROWS*HIDDEN];
__device__ float g_Hi[ROWS*HIDDEN];
__device__ float g_Sc[NBATCH*NHEADS*SEQ*SEQ];   // 128 MB scores/attn
__device__ float g_M [D_MODEL*D_MODEL];
__device__ float g_Ta[D_MODEL*D_MODEL];
__device__ float g_Tb[D_MODEL*D_MODEL];
__device__ float g_Ur[D_MODEL*D_MODEL];
__device__ float g_Ui[D_MODEL*D_MODEL];

// ---------------- tf32 helpers ----------------
__device__ __forceinline__ uint32_t f2tf32(float x) {
    uint32_t r;
    asm("cvt.rna.tf32.f32 %0, %1;" : "=r"(r) : "f"(x));
    return r;
}
__device__ __forceinline__ void mma_tf32(float* d, const uint32_t* a, const uint32_t* b) {
    asm volatile(
        "mma.sync.aligned.m16n8k8.row.col.f32.tf32.tf32.f32 "
        "{%0,%1,%2,%3}, {%4,%5,%6,%7}, {%8,%9}, {%0,%1,%2,%3};\n"
        : "+f"(d[0]), "+f"(d[1]), "+f"(d[2]), "+f"(d[3])
        : "r"(a[0]), "r"(a[1]), "r"(a[2]), "r"(a[3]), "r"(b[0]), "r"(b[1]));
}

// ---------------- tensor-core strided-batched GEMM ----------------
// C[m,n] = (acc ? C[m,n] : 0) + alpha * sum_k A[m*sAm + k*sAk] * B[n*sBn + k*sBk]
// PREC=0: single-pass tf32 (rel err ~3e-4). PREC=1: tf32x3 split (fp32-class).
// Requirements used by host: sAk == 1; K % 32 == 0; M,N guarded.
template<int PREC>
__global__ __launch_bounds__(256) void gemm_tc(
    float* __restrict__ C, const float* __restrict__ A, const float* __restrict__ B,
    int M, int N, int K,
    long long sAm, long long sBn, long long sBk, long long sCm,
    long long aB1, long long aB2, long long bB1, long long bB2,
    long long cB1, long long cB2, int batchDiv,
    float alpha, int accumulate)
{
    constexpr int BM = 128;
    constexpr int BN = PREC ? 64 : 128;
    constexpr int BK = 32;
    constexpr int WM = PREC ? 32 : 64;
    constexpr int WN = 32;
    constexpr int MT = WM / 16;            // 2 or 4
    constexpr int NT = WN / 8;             // 4
    constexpr int WARPS_N = BN / WN;       // 2 or 4

    __shared__ float As[BM][BK+4];
    __shared__ float Bs[BN][BK+4];

    int z = blockIdx.z;
    int zb = z / batchDiv, zh = z % batchDiv;
    A += (long long)zb*aB1 + (long long)zh*aB2;
    B += (long long)zb*bB1 + (long long)zh*bB2;
    C += (long long)zb*cB1 + (long long)zh*cB2;

    int m0 = blockIdx.y * BM, n0 = blockIdx.x * BN;
    int tid = threadIdx.x;
    int lane = tid & 31, w = tid >> 5;
    int wrow = w / WARPS_N, wcol = w % WARPS_N;
    int mbase = wrow * WM, nbase = wcol * WN;
    int lg = lane >> 2, lt = lane & 3;

    float acc[MT][NT][4];
    #pragma unroll
    for (int mt = 0; mt < MT; mt++)
        #pragma unroll
        for (int nt = 0; nt < NT; nt++)
            #pragma unroll
            for (int r = 0; r < 4; r++) acc[mt][nt][r] = 0.f;

    for (int k0 = 0; k0 < K; k0 += BK) {
        // --- load A tile (sAk == 1 always) ---
        #pragma unroll
        for (int i = 0; i < (BM*BK)/256; i++) {
            int flat = i*256 + tid;
            int m = flat >> 5, k = flat & 31;
            int gm = m0 + m;
            float v = 0.f;
            if (gm < M) v = A[(long long)gm*sAm + (k0 + k)];
            As[m][k] = v;
        }
        // --- load B tile ---
        if (sBk == 1) {
            #pragma unroll
            for (int i = 0; i < (BN*BK)/256; i++) {
                int flat = i*256 + tid;
                int n = flat >> 5, k = flat & 31;
                int gn = n0 + n;
                float v = 0.f;
                if (gn < N) v = B[(long long)gn*sBn + (k0 + k)];
                Bs[n][k] = v;
            }
        } else {
            #pragma unroll
            for (int i = 0; i < (BN*BK)/256; i++) {
                int flat = i*256 + tid;
                int k = flat / BN, n = flat % BN;
                int gn = n0 + n;
                float v = 0.f;
                if (gn < N) v = B[(long long)gn*sBn + (long long)(k0 + k)*sBk];
                Bs[n][k] = v;
            }
        }
        __syncthreads();

        #pragma unroll
        for (int kk = 0; kk < BK; kk += 8) {
            uint32_t ah[MT][4], bh[NT][2];
            uint32_t al[PREC ? MT : 1][4], bl[PREC ? NT : 1][2];
            #pragma unroll
            for (int mt = 0; mt < MT; mt++) {
                int r0 = mbase + mt*16 + lg;
                float x0 = As[r0  ][kk+lt];
                float x1 = As[r0+8][kk+lt];
                float x2 = As[r0  ][kk+lt+4];
                float x3 = As[r0+8][kk+lt+4];
                ah[mt][0] = f2tf32(x0); ah[mt][1] = f2tf32(x1);
                ah[mt][2] = f2tf32(x2); ah[mt][3] = f2tf32(x3);
                if (PREC) {
                    al[mt][0] = f2tf32(x0 - __uint_as_float(ah[mt][0]));
                    al[mt][1] = f2tf32(x1 - __uint_as_float(ah[mt][1]));
                    al[mt][2] = f2tf32(x2 - __uint_as_float(ah[mt][2]));
                    al[mt][3] = f2tf32(x3 - __uint_as_float(ah[mt][3]));
                }
            }
            #pragma unroll
            for (int nt = 0; nt < NT; nt++) {
                int c0 = nbase + nt*8 + lg;
                float y0 = Bs[c0][kk+lt];
                float y1 = Bs[c0][kk+lt+4];
                bh[nt][0] = f2tf32(y0); bh[nt][1] = f2tf32(y1);
                if (PREC) {
                    bl[nt][0] = f2tf32(y0 - __uint_as_float(bh[nt][0]));
                    bl[nt][1] = f2tf32(y1 - __uint_as_float(bh[nt][1]));
                }
            }
            #pragma unroll
            for (int mt = 0; mt < MT; mt++)
                #pragma unroll
                for (int nt = 0; nt < NT; nt++) {
                    mma_tf32(acc[mt][nt], ah[mt], bh[nt]);
                    if (PREC) {
                        mma_tf32(acc[mt][nt], ah[mt], bl[nt]);
                        mma_tf32(acc[mt][nt], al[mt], bh[nt]);
                    }
                }
        }
        __syncthreads();
    }

    // --- epilogue ---
    #pragma unroll
    for (int mt = 0; mt < MT; mt++) {
        #pragma unroll
        for (int nt = 0; nt < NT; nt++) {
            #pragma unroll
            for (int r = 0; r < 2; r++) {
                int gm = m0 + mbase + mt*16 + lg + r*8;
                if (gm >= M) continue;
                #pragma unroll
                for (int c = 0; c < 2; c++) {
                    int gn = n0 + nbase + nt*8 + lt*2 + c;
                    if (gn >= N) continue;
                    long long p = (long long)gm*sCm + gn;
                    float v = alpha * acc[mt][nt][r*2 + c];
                    if (accumulate) v += C[p];
                    C[p] = v;
                }
            }
        }
    }
}

// ---------------- 1024-pt complex FFT (radix-2 Stockham), one block/column ----
__global__ __launch_bounds__(512) void fft_kernel(float* __restrict__ re,
                                                  float* __restrict__ im,
                                                  int inverse)
{
    __shared__ float sr[2][1024];
    __shared__ float si[2][1024];
    int col = blockIdx.x;
    int b   = col >> 10;
    int rem = col & 1023;
    long long base = (long long)b * SEQ * D_MODEL + rem;
    int t = threadIdx.x;

    sr[0][t]      = re[base + (long long)t*D_MODEL];
    si[0][t]      = im[base + (long long)t*D_MODEL];
    sr[0][t+512]  = re[base + (long long)(t+512)*D_MODEL];
    si[0][t+512]  = im[base + (long long)(t+512)*D_MODEL];
    __syncthreads();

    float sgn = inverse ? 6.283185307179586f : -6.283185307179586f;
    int cur = 0;
    #pragma unroll
    for (int s = 0; s < 10; s++) {
        int L = 1 << s;
        int l = t & (L-1);
        int r = t >> s;
        float ar = sr[cur][t],     ai = si[cur][t];
        float br = sr[cur][t+512], bi = si[cur][t+512];
        float ang = sgn * (float)l / (float)(2*L);
        float c, sn;
        sincosf(ang, &sn, &c);
        float tr = c*br - sn*bi;
        float ti = c*bi + sn*br;
        int nxt = cur ^ 1;
        int o = r*(2*L) + l;
        sr[nxt][o]   = ar + tr;  si[nxt][o]   = ai + ti;
        sr[nxt][o+L] = ar - tr;  si[nxt][o+L] = ai - ti;
        cur = nxt;
        __syncthreads();
    }
    float sc = inverse ? (1.0f/1024.0f) : 1.0f;
    re[base + (long long)t*D_MODEL]       = sr[cur][t]*sc;
    im[base + (long long)t*D_MODEL]       = si[cur][t]*sc;
    re[base + (long long)(t+512)*D_MODEL] = sr[cur][t+512]*sc;
    im[base + (long long)(t+512)*D_MODEL] = si[cur][t+512]*sc;
}

// ---------------- row softmax over 1024 columns ----------------
__global__ __launch_bounds__(256) void softmax_kernel(float* __restrict__ S)
{
    long long row = blockIdx.x;
    float* p = S + row*1024;
    int t = threadIdx.x;
    __shared__ float red[256];

    float m = -1e30f;
    #pragma unroll
    for (int i = 0; i < 4; i++) m = fmaxf(m, p[t + i*256]);
    red[t] = m; __syncthreads();
    for (int s = 128; s > 0; s >>= 1) { if (t < s) red[t] = fmaxf(red[t], red[t+s]); __syncthreads(); }
    m = red[0]; __syncthreads();

    float vals[4]; float sum = 0.f;
    #pragma unroll
    for (int i = 0; i < 4; i++) { vals[i] = expf(p[t + i*256] - m); sum += vals[i]; }
    red[t] = sum; __syncthreads();
    for (int s = 128; s > 0; s >>= 1) { if (t < s) red[t] += red[t+s]; __syncthreads(); }
    float inv = 1.0f / red[0];
    #pragma unroll
    for (int i = 0; i < 4; i++) p[t + i*256] = vals[i]*inv;
}

// ---------------- elementwise helpers ----------------
__global__ void epilogue_kernel(float* __restrict__ Y, const float* __restrict__ bias,
                                long long total, int Ncols, int gelu)
{
    long long i = (long long)blockIdx.x*blockDim.x + threadIdx.x;
    if (i >= total) return;
    int n = (int)(i % Ncols);
    float v = Y[i] + bias[n];
    if (gelu) v = 0.5f * v * (1.0f + erff(v * 0.7071067811865476f));
    Y[i] = v;
}
__global__ void copy_kernel(float* __restrict__ y, const float* __restrict__ x, long long n)
{
    long long i = (long long)blockIdx.x*blockDim.x + threadIdx.x;
    if (i < n) y[i] = x[i];
}
__global__ void scale_kernel(float* __restrict__ y, const float* __restrict__ x,
                             const float* __restrict__ dt, long long n)
{
    long long i = (long long)blockIdx.x*blockDim.x + threadIdx.x;
    if (i < n) y[i] = x[i]*dt[0];
}
__global__ void initU_kernel(float* __restrict__ Ur, float* __restrict__ Ui)
{
    long long i = (long long)blockIdx.x*blockDim.x + threadIdx.x;
    if (i < (long long)D_MODEL*D_MODEL) {
        Ur[i] = ((i / D_MODEL) == (i % D_MODEL)) ? 1.f : 0.f;
        Ui[i] = 0.f;
    }
}
__global__ void axpy_kernel(float* __restrict__ y, const float* __restrict__ x,
                            float c, long long n)
{
    long long i = (long long)blockIdx.x*blockDim.x + threadIdx.x;
    if (i < n) y[i] += c*x[i];
}

// ---------------- host orchestration ----------------
static void launch_gemm_p(int prec, float* C, const float* A, const float* B,
    int M, int N, int K,
    long long sAm, long long sBn, long long sBk, long long sCm,
    float alpha, int acc,
    int batch = 1, int batchDiv = 1,
    long long aB1 = 0, long long aB2 = 0,
    long long bB1 = 0, long long bB2 = 0,
    long long cB1 = 0, long long cB2 = 0)
{
    int BN = prec ? 64 : 128;
    dim3 grid((N+BN-1)/BN, (M+127)/128, batch);
    if (prec)
        gemm_tc<1><<<grid, 256>>>(C, A, B, M, N, K, sAm, sBn, sBk, sCm,
                                  aB1, aB2, bB1, bB2, cB1, cB2, batchDiv, alpha, acc);
    else
        gemm_tc<0><<<grid, 256>>>(C, A, B, M, N, K, sAm, sBn, sBk, sCm,
                                  aB1, aB2, bB1, bB2, cB1, cB2, batchDiv, alpha, acc);
}

static void launch_epilogue(float* Y, const float* bias, long long rows, int ncols, int gelu)
{
    long long total = rows*(long long)ncols;
    int blocks = (int)((total + 255)/256);
    epilogue_kernel<<<blocks, 256>>>(Y, bias, total, ncols, gelu);
}

// complex linear: (Yr,Yi) = (Xr,Xi) @ (Wr,Wi)^T + (br,bi)
static void clin(int prec, float* Yr, float* Yi,
                 const float* Xr, const float* Xi,
                 const float* Wr, const float* Wi,
                 const float* br, const float* bi,
                 int M, int N, int K, int acc, int gelu)
{
    launch_gemm_p(prec, Yr, Xr, Wr, M, N, K, K, K, 1, N,  1.f, acc);
    launch_gemm_p(prec, Yr, Xi, Wi, M, N, K, K, K, 1, N, -1.f, 1);
    launch_gemm_p(prec, Yi, Xr, Wi, M, N, K, K, K, 1, N,  1.f, acc);
    launch_gemm_p(prec, Yi, Xi, Wr, M, N, K, K, K, 1, N,  1.f, 1);
    launch_epilogue(Yr, br, M, N, gelu);
    launch_epilogue(Yi, bi, M, N, gelu);
}

extern "C" void kernel_launch(void* const* d_in, const int* in_sizes, int n_in,
                              void* d_out, int out_size)
{
    const float* x_real = (const float*)d_in[0];
    const float* x_imag = (const float*)d_in[1];
    const float* Wr_q = (const float*)d_in[2];   const float* Wi_q = (const float*)d_in[3];
    const float* br_q = (const float*)d_in[4];   const float* bi_q = (const float*)d_in[5];
    const float* Wr_k = (const float*)d_in[6];   const float* Wi_k = (const float*)d_in[7];
    const float* br_k = (const float*)d_in[8];   const float* bi_k = (const float*)d_in[9];
    const float* Wr_v = (const float*)d_in[10];  const float* Wi_v = (const float*)d_in[11];
    const float* br_v = (const float*)d_in[12];  const float* bi_v = (const float*)d_in[13];
    const float* Wr_o = (const float*)d_in[14];  const float* Wi_o = (const float*)d_in[15];
    const float* br_o = (const float*)d_in[16];  const float* bi_o = (const float*)d_in[17];
    const float* Wr_f1 = (const float*)d_in[18]; const float* Wi_f1 = (const float*)d_in[19];
    const float* br_f1 = (const float*)d_in[20]; const float* bi_f1 = (const float*)d_in[21];
    const float* Wr_f2 = (const float*)d_in[22]; const float* Wi_f2 = (const float*)d_in[23];
    const float* br_f2 = (const float*)d_in[24]; const float* bi_f2 = (const float*)d_in[25];
    const float* Hmat = (const float*)d_in[26];
    const float* dtp  = (const float*)d_in[27];

    float* outRe = (float*)d_out;
    float* outIm = outRe + (long long)ROWS*D_MODEL;

    float *Qr,*Qi,*Kr,*Ki,*Vr,*Vi,*Xr,*Xi,*Or,*Oi,*Hr,*Hi,*Sc,*Mb,*Ta,*Tb,*Ur,*Ui;
    cudaGetSymbolAddress((void**)&Qr, g_Qr); cudaGetSymbolAddress((void**)&Qi, g_Qi);
    cudaGetSymbolAddress((void**)&Kr, g_Kr); cudaGetSymbolAddress((void**)&Ki, g_Ki);
    cudaGetSymbolAddress((void**)&Vr, g_Vr); cudaGetSymbolAddress((void**)&Vi, g_Vi);
    cudaGetSymbolAddress((void**)&Xr, g_Xr); cudaGetSymbolAddress((void**)&Xi, g_Xi);
    cudaGetSymbolAddress((void**)&Or, g_Or); cudaGetSymbolAddress((void**)&Oi, g_Oi);
    cudaGetSymbolAddress((void**)&Hr, g_Hr); cudaGetSymbolAddress((void**)&Hi, g_Hi);
    cudaGetSymbolAddress((void**)&Sc, g_Sc);
    cudaGetSymbolAddress((void**)&Mb, g_M);  cudaGetSymbolAddress((void**)&Ta, g_Ta);
    cudaGetSymbolAddress((void**)&Tb, g_Tb);
    cudaGetSymbolAddress((void**)&Ur, g_Ur); cudaGetSymbolAddress((void**)&Ui, g_Ui);

    const long long ND = (long long)ROWS*D_MODEL;
    copy_kernel<<<(int)((ND+255)/256), 256>>>(Xr, x_real, ND);
    copy_kernel<<<(int)((ND+255)/256), 256>>>(Xi, x_imag, ND);

    // ---- Q/K/V projections.  Q/K precise (softmax logit sensitivity), V fast. ----
    clin(1, Qr, Qi, Xr, Xi, Wr_q, Wi_q, br_q, bi_q, ROWS, D_MODEL, D_MODEL, 0, 0);
    clin(1, Kr, Ki, Xr, Xi, Wr_k, Wi_k, br_k, bi_k, ROWS, D_MODEL, D_MODEL, 0, 0);
    clin(0, Vr, Vi, Xr, Xi, Wr_v, Wi_v, br_v, bi_v, ROWS, D_MODEL, D_MODEL, 0, 0);

    // ---- forward FFT along sequence axis ----
    fft_kernel<<<NBATCH*D_MODEL, 512>>>(Qr, Qi, 0);
    fft_kernel<<<NBATCH*D_MODEL, 512>>>(Kr, Ki, 0);
    fft_kernel<<<NBATCH*D_MODEL, 512>>>(Vr, Vi, 0);

    // ---- scores.real = scale*(Qfr Kfr^T + Qfi Kfi^T), batched over (b,h); precise ----
    {
        const float scale = 0.125f; // 1/sqrt(64)
        long long hM = (long long)SEQ*SEQ;
        launch_gemm_p(1, Sc, Qr, Kr, SEQ, SEQ, DHEAD,
                    D_MODEL, D_MODEL, 1, SEQ, scale, 0,
                    NBATCH*NHEADS, NHEADS,
                    (long long)SEQ*D_MODEL, DHEAD,
                    (long long)SEQ*D_MODEL, DHEAD,
                    (long long)NHEADS*hM, hM);
        launch_gemm_p(1, Sc, Qi, Ki, SEQ, SEQ, DHEAD,
                    D_MODEL, D_MODEL, 1, SEQ, scale, 1,
                    NBATCH*NHEADS, NHEADS,
                    (long long)SEQ*D_MODEL, DHEAD,
                    (long long)SEQ*D_MODEL, DHEAD,
                    (long long)NHEADS*hM, hM);
    }

    softmax_kernel<<<NBATCH*NHEADS*SEQ, 256>>>(Sc);

    // ---- out_f = attn @ Vf (attn real); fast tf32, B is k-strided (sBn=1) ----
    {
        long long hM = (long long)SEQ*SEQ;
        launch_gemm_p(0, Or, Sc, Vr, SEQ, DHEAD, SEQ,
                    SEQ, 1, D_MODEL, D_MODEL, 1.f, 0,
                    NBATCH*NHEADS, NHEADS,
                    (long long)NHEADS*hM, hM,
                    (long long)SEQ*D_MODEL, DHEAD,
                    (long long)SEQ*D_MODEL, DHEAD);
        launch_gemm_p(0, Oi, Sc, Vi, SEQ, DHEAD, SEQ,
                    SEQ, 1, D_MODEL, D_MODEL, 1.f, 0,
                    NBATCH*NHEADS, NHEADS,
                    (long long)NHEADS*hM, hM,
                    (long long)SEQ*D_MODEL, DHEAD,
                    (long long)SEQ*D_MODEL, DHEAD);
    }

    // ---- inverse FFT ----
    fft_kernel<<<NBATCH*D_MODEL, 512>>>(Or, Oi, 1);

    // ---- x += clin(out, Wo); fast ----
    launch_gemm_p(0, Xr, Or, Wr_o, ROWS, D_MODEL, D_MODEL, D_MODEL, D_MODEL, 1, D_MODEL,  1.f, 1);
    launch_gemm_p(0, Xr, Oi, Wi_o, ROWS, D_MODEL, D_MODEL, D_MODEL, D_MODEL, 1, D_MODEL, -1.f, 1);
    launch_gemm_p(0, Xi, Or, Wi_o, ROWS, D_MODEL, D_MODEL, D_MODEL, D_MODEL, 1, D_MODEL,  1.f, 1);
    launch_gemm_p(0, Xi, Oi, Wr_o, ROWS, D_MODEL, D_MODEL, D_MODEL, D_MODEL, 1, D_MODEL,  1.f, 1);
    launch_epilogue(Xr, br_o, ROWS, D_MODEL, 0);
    launch_epilogue(Xi, bi_o, ROWS, D_MODEL, 0);

    // ---- FFN; fast ----
    clin(0, Hr, Hi, Xr, Xi, Wr_f1, Wi_f1, br_f1, bi_f1, ROWS, HIDDEN, D_MODEL, 0, 1);
    launch_gemm_p(0, Xr, Hr, Wr_f2, ROWS, D_MODEL, HIDDEN, HIDDEN, HIDDEN, 1, D_MODEL,  1.f, 1);
    launch_gemm_p(0, Xr, Hi, Wi_f2, ROWS, D_MODEL, HIDDEN, HIDDEN, HIDDEN, 1, D_MODEL, -1.f, 1);
    launch_gemm_p(0, Xi, Hr, Wi_f2, ROWS, D_MODEL, HIDDEN, HIDDEN, HIDDEN, 1, D_MODEL,  1.f, 1);
    launch_gemm_p(0, Xi, Hi, Wr_f2, ROWS, D_MODEL, HIDDEN, HIDDEN, HIDDEN, 1, D_MODEL,  1.f, 1);
    launch_epilogue(Xr, br_f2, ROWS, D_MODEL, 0);
    launch_epilogue(Xi, bi_f2, ROWS, D_MODEL, 0);

    // ---- U = expm(-i H dt) via Taylor; powers fast tf32 ----
    const long long DD = (long long)D_MODEL*D_MODEL;
    scale_kernel<<<(int)((DD+255)/256), 256>>>(Mb, Hmat, dtp, DD);
    initU_kernel<<<(int)((DD+255)/256), 256>>>(Ur, Ui);
    axpy_kernel<<<(int)((DD+255)/256), 256>>>(Ui, Mb, -1.0f, DD);
    {
        float* prev = Mb;
        float* bufs[2] = { Ta, Tb };
        const int   tgt [5] = { 0, 1, 0, 1, 0 };
        const float coef[5] = { -0.5f, 1.0f/6.0f, 1.0f/24.0f, -1.0f/120.0f, -1.0f/720.0f };
        for (int s = 0; s < 5; s++) {
            float* dst = bufs[s & 1];
            launch_gemm_p(0, dst, prev, Mb, D_MODEL, D_MODEL, D_MODEL,
                        D_MODEL, D_MODEL, 1, D_MODEL, 1.f, 0);
            axpy_kernel<<<(int)((DD+255)/256), 256>>>(tgt[s] ? Ui : Ur, dst, coef[s], DD);
            prev = dst;
        }
    }

    // ---- out = x @ U (U symmetric => NT form); precise (final output) ----
    launch_gemm_p(1, outRe, Xr, Ur, ROWS, D_MODEL, D_MODEL, D_MODEL, D_MODEL, 1, D_MODEL,  1.f, 0);
    launch_gemm_p(1, outRe, Xi, Ui, ROWS, D_MODEL, D_MODEL, D_MODEL, D_MODEL, 1, D_MODEL, -1.f, 1);
    launch_gemm_p(1, outIm, Xr, Ui, ROWS, D_MODEL, D_MODEL, D_MODEL, D_MODEL, 1, D_MODEL,  1.f, 0);
    launch_gemm_p(1, outIm, Xi, Ur, ROWS, D_MODEL, D_MODEL, D_MODEL, D_MODEL, 1, D_MODEL,  1.f, 1);
}

// round 3
// speedup vs baseline: 2.6419x; 1.9221x over previous
#include <cuda_runtime.h>
#include <math.h>
#include <stdint.h>

#define SEQ     1024
#define D_MODEL 1024
#define NHEADS  16
#define DHEAD   64
#define HIDDEN  4096
#define NBATCH  2
#define ROWS    (NBATCH*SEQ)   // 2048

// ---------------- scratch (device statics; no allocation) ----------------
__device__ __align__(128) float g_Qr[ROWS*D_MODEL];
__device__ __align__(128) float g_Qi[ROWS*D_MODEL];
__device__ __align__(128) float g_Kr[ROWS*D_MODEL];
__device__ __align__(128) float g_Ki[ROWS*D_MODEL];
__device__ __align__(128) float g_Vr[ROWS*D_MODEL];
__device__ __align__(128) float g_Vi[ROWS*D_MODEL];
__device__ __align__(128) float g_Xr[ROWS*D_MODEL];
__device__ __align__(128) float g_Xi[ROWS*D_MODEL];
__device__ __align__(128) float g_Or[ROWS*D_MODEL];
__device__ __align__(128) float g_Oi[ROWS*D_MODEL];
__device__ __align__(128) float g_Hr[ROWS*HIDDEN];
__device__ __align__(128) float g_Hi[ROWS*HIDDEN];
__device__ __align__(128) float g_Sc[NBATCH*NHEADS*SEQ*SEQ];
__device__ __align__(128) float g_M [D_MODEL*D_MODEL];
__device__ __align__(128) float g_Ta[D_MODEL*D_MODEL];
__device__ __align__(128) float g_Tb[D_MODEL*D_MODEL];
__device__ __align__(128) float g_Ur[D_MODEL*D_MODEL];
__device__ __align__(128) float g_Ui[D_MODEL*D_MODEL];

// ---------------- tf32 helpers ----------------
__device__ __forceinline__ uint32_t f2tf32(float x) {
    uint32_t r;
    asm("cvt.rna.tf32.f32 %0, %1;" : "=r"(r) : "f"(x));
    return r;
}
__device__ __forceinline__ void mma_tf32(float* d, const uint32_t* a, const uint32_t* b) {
    asm volatile(
        "mma.sync.aligned.m16n8k8.row.col.f32.tf32.tf32.f32 "
        "{%0,%1,%2,%3}, {%4,%5,%6,%7}, {%8,%9}, {%0,%1,%2,%3};\n"
        : "+f"(d[0]), "+f"(d[1]), "+f"(d[2]), "+f"(d[3])
        : "r"(a[0]), "r"(a[1]), "r"(a[2]), "r"(a[3]), "r"(b[0]), "r"(b[1]));
}
__device__ __forceinline__ float gelu_f(float v) {
    return 0.5f * v * (1.0f + erff(v * 0.7071067811865476f));
}

// ================= unified complex tensor-core GEMM =================
// MODE 0: REAL       C  = alpha*(Ar.Br^T)                 (+C)
// MODE 1: COMPLEX    Cr = Ar.Br^T - Ai.Bi^T (+bias,gelu)  (+Cr)
//                    Ci = Ar.Bi^T + Ai.Br^T
// MODE 2: CONJ_REAL  C  = alpha*(Ar.Br^T + Ai.Bi^T)       (+C)
// MODE 3: REAL_A     Cr = Ar.Br^T ; Ci = Ar.Bi^T
// A[m,k]: Ar[m*sAm + k] (k contiguous, guaranteed).
// B[n,k]: Br[n*sBn + k*sBk] (sBk==1 or n-contiguous with sBn==1).
// All of M%128, N%64, K%32 == 0 (guaranteed by caller).
#define MMAX(d, ah, al, bh, bl) do { \
    mma_tf32(d, ah, bh); \
    if (PREC) { mma_tf32(d, ah, bl); mma_tf32(d, al, bh); } } while (0)

template<int MODE, int PREC>
__global__ __launch_bounds__(256, 1) void cgemm(
    float* __restrict__ Cr, float* __restrict__ Ci,
    const float* __restrict__ Ar, const float* __restrict__ Ai,
    const float* __restrict__ Br, const float* __restrict__ Bi,
    int M, int N, int K,
    long long sAm, long long sBn, long long sBk, long long sCm,
    long long aB1, long long aB2, long long bB1, long long bB2,
    long long cB1, long long cB2, int batchDiv,
    float alpha, int accumulate,
    const float* __restrict__ biasR, const float* __restrict__ biasI, int gelu)
{
    constexpr bool AC = (MODE == 1 || MODE == 2);          // A complex
    constexpr bool BC = (MODE >= 1);                       // B complex
    constexpr bool CC = (MODE == 1 || MODE == 3);          // C complex
    constexpr int BM = 128, BN = 64, BK = 32, LDS = 36;
    constexpr int MT = 2, NT = 4;                          // WM=32, WN=32, warps 4x2
    constexpr int ATW = BM * LDS, BTW = BN * LDS;
    constexpr int nA = AC ? 2 : 1, nB = BC ? 2 : 1;
    constexpr int HIW = nA * ATW + nB * BTW;               // lo plane offset (words)

    extern __shared__ uint32_t sm[];
    uint32_t* sAr = sm;
    uint32_t* sAi = sm + ATW;
    uint32_t* sBr = sm + nA * ATW;
    uint32_t* sBi = sBr + BTW;

    int z = blockIdx.z, zb = z / batchDiv, zh = z % batchDiv;
    Ar += (long long)zb * aB1 + (long long)zh * aB2;
    if constexpr (AC) Ai += (long long)zb * aB1 + (long long)zh * aB2;
    Br += (long long)zb * bB1 + (long long)zh * bB2;
    if constexpr (BC) Bi += (long long)zb * bB1 + (long long)zh * bB2;
    Cr += (long long)zb * cB1 + (long long)zh * cB2;
    if constexpr (CC) Ci += (long long)zb * cB1 + (long long)zh * cB2;

    int m0 = blockIdx.y * BM, n0 = blockIdx.x * BN;
    int tid = threadIdx.x;
    int lane = tid & 31, w = tid >> 5;
    int mbase = (w >> 1) * 32, nbase = (w & 1) * 32;
    int lg = lane >> 2, lt = lane & 3;

    float accP[MT][NT][4], accM[MT][NT][4], accI[MT][NT][4];
    #pragma unroll
    for (int mt = 0; mt < MT; mt++)
        #pragma unroll
        for (int nt = 0; nt < NT; nt++)
            #pragma unroll
            for (int e = 0; e < 4; e++) {
                accP[mt][nt][e] = 0.f; accM[mt][nt][e] = 0.f; accI[mt][nt][e] = 0.f;
            }

    for (int k0 = 0; k0 < K; k0 += BK) {
        // ---- A tiles: float4 along k, convert at store ----
        auto loadA = [&](const float* G, uint32_t* SH) {
            #pragma unroll
            for (int i = 0; i < 4; i++) {
                int idx = i * 256 + tid;
                int row = idx >> 3, c4 = idx & 7;
                const float4 v = *(const float4*)(G + (long long)(m0 + row) * sAm + k0 + c4 * 4);
                float xs[4] = { v.x, v.y, v.z, v.w };
                uint32_t* p = SH + row * LDS + c4 * 4;
                #pragma unroll
                for (int j = 0; j < 4; j++) {
                    uint32_t h = f2tf32(xs[j]);
                    p[j] = h;
                    if (PREC) p[j + HIW] = f2tf32(xs[j] - __uint_as_float(h));
                }
            }
        };
        // ---- B tiles, k-contiguous ----
        auto loadBc = [&](const float* G, uint32_t* SH) {
            #pragma unroll
            for (int i = 0; i < 2; i++) {
                int idx = i * 256 + tid;
                int row = idx >> 3, c4 = idx & 7;
                const float4 v = *(const float4*)(G + (long long)(n0 + row) * sBn + k0 + c4 * 4);
                float xs[4] = { v.x, v.y, v.z, v.w };
                uint32_t* p = SH + row * LDS + c4 * 4;
                #pragma unroll
                for (int j = 0; j < 4; j++) {
                    uint32_t h = f2tf32(xs[j]);
                    p[j] = h;
                    if (PREC) p[j + HIW] = f2tf32(xs[j] - __uint_as_float(h));
                }
            }
        };
        // ---- B tiles, n-contiguous (transpose on store) ----
        auto loadBs = [&](const float* G, uint32_t* SH) {
            #pragma unroll
            for (int i = 0; i < 2; i++) {
                int idx = i * 256 + tid;
                int k = idx >> 4, c4 = idx & 15;
                const float4 v = *(const float4*)(G + (long long)(k0 + k) * sBk + n0 + c4 * 4);
                float xs[4] = { v.x, v.y, v.z, v.w };
                #pragma unroll
                for (int j = 0; j < 4; j++) {
                    uint32_t h = f2tf32(xs[j]);
                    int o = (c4 * 4 + j) * LDS + k;
                    SH[o] = h;
                    if (PREC) SH[o + HIW] = f2tf32(xs[j] - __uint_as_float(h));
                }
            }
        };

        loadA(Ar, sAr);
        if constexpr (AC) loadA(Ai, sAi);
        if (sBk == 1) {
            loadBc(Br, sBr);
            if constexpr (BC) loadBc(Bi, sBi);
        } else {
            loadBs(Br, sBr);
            if constexpr (BC) loadBs(Bi, sBi);
        }
        __syncthreads();

        #pragma unroll
        for (int kk = 0; kk < BK; kk += 8) {
            uint32_t arH[MT][4], aiH[MT][4], arL[MT][4], aiL[MT][4];
            uint32_t brH[NT][2], biH[NT][2], brL[NT][2], biL[NT][2];
            #pragma unroll
            for (int mt = 0; mt < MT; mt++) {
                int o0 = (mbase + mt * 16 + lg) * LDS + kk + lt;
                int o1 = o0 + 8 * LDS;
                arH[mt][0] = sAr[o0];   arH[mt][1] = sAr[o1];
                arH[mt][2] = sAr[o0+4]; arH[mt][3] = sAr[o1+4];
                if (PREC) {
                    arL[mt][0] = sAr[o0+HIW];   arL[mt][1] = sAr[o1+HIW];
                    arL[mt][2] = sAr[o0+4+HIW]; arL[mt][3] = sAr[o1+4+HIW];
                }
                if constexpr (AC) {
                    aiH[mt][0] = sAi[o0];   aiH[mt][1] = sAi[o1];
                    aiH[mt][2] = sAi[o0+4]; aiH[mt][3] = sAi[o1+4];
                    if (PREC) {
                        aiL[mt][0] = sAi[o0+HIW];   aiL[mt][1] = sAi[o1+HIW];
                        aiL[mt][2] = sAi[o0+4+HIW]; aiL[mt][3] = sAi[o1+4+HIW];
                    }
                }
            }
            #pragma unroll
            for (int nt = 0; nt < NT; nt++) {
                int o0 = (nbase + nt * 8 + lg) * LDS + kk + lt;
                brH[nt][0] = sBr[o0]; brH[nt][1] = sBr[o0+4];
                if (PREC) { brL[nt][0] = sBr[o0+HIW]; brL[nt][1] = sBr[o0+4+HIW]; }
                if constexpr (BC) {
                    biH[nt][0] = sBi[o0]; biH[nt][1] = sBi[o0+4];
                    if (PREC) { biL[nt][0] = sBi[o0+HIW]; biL[nt][1] = sBi[o0+4+HIW]; }
                }
            }
            #pragma unroll
            for (int mt = 0; mt < MT; mt++)
                #pragma unroll
                for (int nt = 0; nt < NT; nt++) {
                    if constexpr (MODE == 0) {
                        MMAX(accP[mt][nt], arH[mt], arL[mt], brH[nt], brL[nt]);
                    } else if constexpr (MODE == 1) {
                        MMAX(accP[mt][nt], arH[mt], arL[mt], brH[nt], brL[nt]);
                        MMAX(accM[mt][nt], aiH[mt], aiL[mt], biH[nt], biL[nt]);
                        MMAX(accI[mt][nt], arH[mt], arL[mt], biH[nt], biL[nt]);
                        MMAX(accI[mt][nt], aiH[mt], aiL[mt], brH[nt], brL[nt]);
                    } else if constexpr (MODE == 2) {
                        MMAX(accP[mt][nt], arH[mt], arL[mt], brH[nt], brL[nt]);
                        MMAX(accP[mt][nt], aiH[mt], aiL[mt], biH[nt], biL[nt]);
                    } else {
                        MMAX(accP[mt][nt], arH[mt], arL[mt], brH[nt], brL[nt]);
                        MMAX(accI[mt][nt], arH[mt], arL[mt], biH[nt], biL[nt]);
                    }
                }
        }
        __syncthreads();
    }

    // ---- epilogue ----
    #pragma unroll
    for (int mt = 0; mt < MT; mt++)
        #pragma unroll
        for (int nt = 0; nt < NT; nt++)
            #pragma unroll
            for (int e = 0; e < 4; e++) {
                int gm = m0 + mbase + mt * 16 + lg + (e >> 1) * 8;
                int gn = n0 + nbase + nt * 8 + lt * 2 + (e & 1);
                long long p = (long long)gm * sCm + gn;
                if constexpr (MODE == 1) {
                    float vr = accP[mt][nt][e] - accM[mt][nt][e];
                    float vi = accI[mt][nt][e];
                    if (biasR) { vr += biasR[gn]; vi += biasI[gn]; }
                    if (gelu)  { vr = gelu_f(vr); vi = gelu_f(vi); }
                    if (accumulate) { vr += Cr[p]; vi += Ci[p]; }
                    Cr[p] = vr; Ci[p] = vi;
                } else if constexpr (MODE == 3) {
                    Cr[p] = accP[mt][nt][e];
                    Ci[p] = accI[mt][nt][e];
                } else {
                    float v = alpha * accP[mt][nt][e];
                    if (accumulate) v += Cr[p];
                    Cr[p] = v;
                }
            }
}

// ---------------- 1024-pt complex FFT (radix-2 Stockham) ----------------
__global__ __launch_bounds__(512) void fft_kernel(float* __restrict__ re,
                                                  float* __restrict__ im,
                                                  int inverse)
{
    __shared__ float sr[2][1024];
    __shared__ float si[2][1024];
    int col = blockIdx.x;
    int b   = col >> 10;
    int rem = col & 1023;
    long long base = (long long)b * SEQ * D_MODEL + rem;
    int t = threadIdx.x;

    sr[0][t]      = re[base + (long long)t*D_MODEL];
    si[0][t]      = im[base + (long long)t*D_MODEL];
    sr[0][t+512]  = re[base + (long long)(t+512)*D_MODEL];
    si[0][t+512]  = im[base + (long long)(t+512)*D_MODEL];
    __syncthreads();

    float sgn = inverse ? 6.283185307179586f : -6.283185307179586f;
    int cur = 0;
    #pragma unroll
    for (int s = 0; s < 10; s++) {
        int L = 1 << s;
        int l = t & (L-1);
        int r = t >> s;
        float ar = sr[cur][t],     ai = si[cur][t];
        float br = sr[cur][t+512], bi = si[cur][t+512];
        float ang = sgn * (float)l / (float)(2*L);
        float c, sn;
        sincosf(ang, &sn, &c);
        float tr = c*br - sn*bi;
        float ti = c*bi + sn*br;
        int nxt = cur ^ 1;
        int o = r*(2*L) + l;
        sr[nxt][o]   = ar + tr;  si[nxt][o]   = ai + ti;
        sr[nxt][o+L] = ar - tr;  si[nxt][o+L] = ai - ti;
        cur = nxt;
        __syncthreads();
    }
    float sc = inverse ? (1.0f/1024.0f) : 1.0f;
    re[base + (long long)t*D_MODEL]       = sr[cur][t]*sc;
    im[base + (long long)t*D_MODEL]       = si[cur][t]*sc;
    re[base + (long long)(t+512)*D_MODEL] = sr[cur][t+512]*sc;
    im[base + (long long)(t+512)*D_MODEL] = si[cur][t+512]*sc;
}

// ---------------- row softmax over 1024 columns ----------------
__global__ __launch_bounds__(256) void softmax_kernel(float* __restrict__ S)
{
    long long row = blockIdx.x;
    float* p = S + row*1024;
    int t = threadIdx.x;
    __shared__ float red[256];

    float m = -1e30f;
    #pragma unroll
    for (int i = 0; i < 4; i++) m = fmaxf(m, p[t + i*256]);
    red[t] = m; __syncthreads();
    for (int s = 128; s > 0; s >>= 1) { if (t < s) red[t] = fmaxf(red[t], red[t+s]); __syncthreads(); }
    m = red[0]; __syncthreads();

    float vals[4]; float sum = 0.f;
    #pragma unroll
    for (int i = 0; i < 4; i++) { vals[i] = expf(p[t + i*256] - m); sum += vals[i]; }
    red[t] = sum; __syncthreads();
    for (int s = 128; s > 0; s >>= 1) { if (t < s) red[t] += red[t+s]; __syncthreads(); }
    float inv = 1.0f / red[0];
    #pragma unroll
    for (int i = 0; i < 4; i++) p[t + i*256] = vals[i]*inv;
}

// ---------------- elementwise helpers ----------------
__global__ void copy_kernel(float* __restrict__ y, const float* __restrict__ x, long long n)
{
    long long i = (long long)blockIdx.x*blockDim.x + threadIdx.x;
    if (i < n) y[i] = x[i];
}
__global__ void scale_kernel(float* __restrict__ y, const float* __restrict__ x,
                             const float* __restrict__ dt, long long n)
{
    long long i = (long long)blockIdx.x*blockDim.x + threadIdx.x;
    if (i < n) y[i] = x[i]*dt[0];
}
__global__ void initU_kernel(float* __restrict__ Ur, float* __restrict__ Ui)
{
    long long i = (long long)blockIdx.x*blockDim.x + threadIdx.x;
    if (i < (long long)D_MODEL*D_MODEL) {
        Ur[i] = ((i / D_MODEL) == (i % D_MODEL)) ? 1.f : 0.f;
        Ui[i] = 0.f;
    }
}
__global__ void axpy_kernel(float* __restrict__ y, const float* __restrict__ x,
                            float c, long long n)
{
    long long i = (long long)blockIdx.x*blockDim.x + threadIdx.x;
    if (i < n) y[i] += c*x[i];
}

// ---------------- host orchestration ----------------
static size_t cg_smem(int mode, int prec)
{
    bool AC = (mode == 1 || mode == 2), BC = (mode >= 1);
    int nA = AC ? 2 : 1, nB = BC ? 2 : 1;
    return (size_t)(nA * 128 + nB * 64) * 36 * 4 * (prec ? 2 : 1);
}

static void cg(int mode, int prec,
    float* Cr, float* Ci,
    const float* Ar, const float* Ai,
    const float* Br, const float* Bi,
    int M, int N, int K,
    long long sAm, long long sBn, long long sBk, long long sCm,
    float alpha, int acc,
    const float* bR = nullptr, const float* bI = nullptr, int gelu = 0,
    int batch = 1, int batchDiv = 1,
    long long aB1 = 0, long long aB2 = 0,
    long long bB1 = 0, long long bB2 = 0,
    long long cB1 = 0, long long cB2 = 0)
{
    dim3 grid(N / 64, M / 128, batch);
    size_t sh = cg_smem(mode, prec);
    #define ARGS Cr, Ci, Ar, Ai, Br, Bi, M, N, K, sAm, sBn, sBk, sCm, \
                 aB1, aB2, bB1, bB2, cB1, cB2, batchDiv, alpha, acc, bR, bI, gelu
    if      (mode == 1 && prec == 1) cgemm<1,1><<<grid, 256, sh>>>(ARGS);
    else if (mode == 1 && prec == 0) cgemm<1,0><<<grid, 256, sh>>>(ARGS);
    else if (mode == 2 && prec == 1) cgemm<2,1><<<grid, 256, sh>>>(ARGS);
    else if (mode == 3 && prec == 0) cgemm<3,0><<<grid, 256, sh>>>(ARGS);
    else                             cgemm<0,0><<<grid, 256, sh>>>(ARGS);
    #undef ARGS
}

extern "C" void kernel_launch(void* const* d_in, const int* in_sizes, int n_in,
                              void* d_out, int out_size)
{
    cudaFuncSetAttribute(cgemm<1,1>, cudaFuncAttributeMaxDynamicSharedMemorySize, 110592);
    cudaFuncSetAttribute(cgemm<2,1>, cudaFuncAttributeMaxDynamicSharedMemorySize, 110592);
    cudaFuncSetAttribute(cgemm<1,0>, cudaFuncAttributeMaxDynamicSharedMemorySize, 55296);
    cudaFuncSetAttribute(cgemm<3,0>, cudaFuncAttributeMaxDynamicSharedMemorySize, 36864);
    cudaFuncSetAttribute(cgemm<0,0>, cudaFuncAttributeMaxDynamicSharedMemorySize, 27648);

    const float* x_real = (const float*)d_in[0];
    const float* x_imag = (const float*)d_in[1];
    const float* Wr_q = (const float*)d_in[2];   const float* Wi_q = (const float*)d_in[3];
    const float* br_q = (const float*)d_in[4];   const float* bi_q = (const float*)d_in[5];
    const float* Wr_k = (const float*)d_in[6];   const float* Wi_k = (const float*)d_in[7];
    const float* br_k = (const float*)d_in[8];   const float* bi_k = (const float*)d_in[9];
    const float* Wr_v = (const float*)d_in[10];  const float* Wi_v = (const float*)d_in[11];
    const float* br_v = (const float*)d_in[12];  const float* bi_v = (const float*)d_in[13];
    const float* Wr_o = (const float*)d_in[14];  const float* Wi_o = (const float*)d_in[15];
    const float* br_o = (const float*)d_in[16];  const float* bi_o = (const float*)d_in[17];
    const float* Wr_f1 = (const float*)d_in[18]; const float* Wi_f1 = (const float*)d_in[19];
    const float* br_f1 = (const float*)d_in[20]; const float* bi_f1 = (const float*)d_in[21];
    const float* Wr_f2 = (const float*)d_in[22]; const float* Wi_f2 = (const float*)d_in[23];
    const float* br_f2 = (const float*)d_in[24]; const float* bi_f2 = (const float*)d_in[25];
    const float* Hmat = (const float*)d_in[26];
    const float* dtp  = (const float*)d_in[27];

    float* outRe = (float*)d_out;
    float* outIm = outRe + (long long)ROWS*D_MODEL;

    float *Qr,*Qi,*Kr,*Ki,*Vr,*Vi,*Xr,*Xi,*Or,*Oi,*Hr,*Hi,*Sc,*Mb,*Ta,*Tb,*Ur,*Ui;
    cudaGetSymbolAddress((void**)&Qr, g_Qr); cudaGetSymbolAddress((void**)&Qi, g_Qi);
    cudaGetSymbolAddress((void**)&Kr, g_Kr); cudaGetSymbolAddress((void**)&Ki, g_Ki);
    cudaGetSymbolAddress((void**)&Vr, g_Vr); cudaGetSymbolAddress((void**)&Vi, g_Vi);
    cudaGetSymbolAddress((void**)&Xr, g_Xr); cudaGetSymbolAddress((void**)&Xi, g_Xi);
    cudaGetSymbolAddress((void**)&Or, g_Or); cudaGetSymbolAddress((void**)&Oi, g_Oi);
    cudaGetSymbolAddress((void**)&Hr, g_Hr); cudaGetSymbolAddress((void**)&Hi, g_Hi);
    cudaGetSymbolAddress((void**)&Sc, g_Sc);
    cudaGetSymbolAddress((void**)&Mb, g_M);  cudaGetSymbolAddress((void**)&Ta, g_Ta);
    cudaGetSymbolAddress((void**)&Tb, g_Tb);
    cudaGetSymbolAddress((void**)&Ur, g_Ur); cudaGetSymbolAddress((void**)&Ui, g_Ui);

    const long long ND = (long long)ROWS*D_MODEL;
    const long long DD = (long long)D_MODEL*D_MODEL;
    const long long hM = (long long)SEQ*SEQ;
    copy_kernel<<<(int)((ND+255)/256), 256>>>(Xr, x_real, ND);
    copy_kernel<<<(int)((ND+255)/256), 256>>>(Xi, x_imag, ND);

    // ---- Q/K/V projections (Q/K precise for softmax logit sensitivity) ----
    cg(1,1, Qr,Qi, Xr,Xi, Wr_q,Wi_q, ROWS,D_MODEL,D_MODEL, D_MODEL,D_MODEL,1,D_MODEL, 1.f,0, br_q,bi_q,0);
    cg(1,1, Kr,Ki, Xr,Xi, Wr_k,Wi_k, ROWS,D_MODEL,D_MODEL, D_MODEL,D_MODEL,1,D_MODEL, 1.f,0, br_k,bi_k,0);
    cg(1,0, Vr,Vi, Xr,Xi, Wr_v,Wi_v, ROWS,D_MODEL,D_MODEL, D_MODEL,D_MODEL,1,D_MODEL, 1.f,0, br_v,bi_v,0);

    // ---- forward FFT along sequence axis ----
    fft_kernel<<<NBATCH*D_MODEL, 512>>>(Qr, Qi, 0);
    fft_kernel<<<NBATCH*D_MODEL, 512>>>(Kr, Ki, 0);
    fft_kernel<<<NBATCH*D_MODEL, 512>>>(Vr, Vi, 0);

    // ---- scores = scale*Re(Qf conj(Kf)) = scale*(QfrKfr^T + QfiKfi^T); precise ----
    cg(2,1, Sc,nullptr, Qr,Qi, Kr,Ki, SEQ,SEQ,DHEAD,
       D_MODEL,D_MODEL,1,SEQ, 0.125f,0, nullptr,nullptr,0,
       NBATCH*NHEADS, NHEADS,
       (long long)SEQ*D_MODEL, DHEAD,
       (long long)SEQ*D_MODEL, DHEAD,
       (long long)NHEADS*hM, hM);

    softmax_kernel<<<NBATCH*NHEADS*SEQ, 256>>>(Sc);

    // ---- out_f = attn @ Vf (attn real, V complex, B n-contiguous) ----
    cg(3,0, Or,Oi, Sc,nullptr, Vr,Vi, SEQ,DHEAD,SEQ,
       SEQ,1,D_MODEL,D_MODEL, 1.f,0, nullptr,nullptr,0,
       NBATCH*NHEADS, NHEADS,
       (long long)NHEADS*hM, hM,
       (long long)SEQ*D_MODEL, DHEAD,
       (long long)SEQ*D_MODEL, DHEAD);

    // ---- inverse FFT ----
    fft_kernel<<<NBATCH*D_MODEL, 512>>>(Or, Oi, 1);

    // ---- x += clin(out, Wo) ----
    cg(1,0, Xr,Xi, Or,Oi, Wr_o,Wi_o, ROWS,D_MODEL,D_MODEL, D_MODEL,D_MODEL,1,D_MODEL, 1.f,1, br_o,bi_o,0);

    // ---- FFN ----
    cg(1,0, Hr,Hi, Xr,Xi, Wr_f1,Wi_f1, ROWS,HIDDEN,D_MODEL, D_MODEL,D_MODEL,1,HIDDEN, 1.f,0, br_f1,bi_f1,1);
    cg(1,0, Xr,Xi, Hr,Hi, Wr_f2,Wi_f2, ROWS,D_MODEL,HIDDEN, HIDDEN,HIDDEN,1,D_MODEL, 1.f,1, br_f2,bi_f2,0);

    // ---- U = expm(-i H dt) via Taylor (||H dt||~0.05) ----
    scale_kernel<<<(int)((DD+255)/256), 256>>>(Mb, Hmat, dtp, DD);
    initU_kernel<<<(int)((DD+255)/256), 256>>>(Ur, Ui);
    axpy_kernel<<<(int)((DD+255)/256), 256>>>(Ui, Mb, -1.0f, DD);
    {
        float* prev = Mb;
        float* bufs[2] = { Ta, Tb };
        const int   tgt [5] = { 0, 1, 0, 1, 0 };
        const float coef[5] = { -0.5f, 1.0f/6.0f, 1.0f/24.0f, -1.0f/120.0f, -1.0f/720.0f };
        for (int s = 0; s < 5; s++) {
            float* dst = bufs[s & 1];
            cg(0,0, dst,nullptr, prev,nullptr, Mb,nullptr,
               D_MODEL,D_MODEL,D_MODEL, D_MODEL,D_MODEL,1,D_MODEL, 1.f,0);
            axpy_kernel<<<(int)((DD+255)/256), 256>>>(tgt[s] ? Ui : Ur, dst, coef[s], DD);
            prev = dst;
        }
    }

    // ---- out = x @ U (U symmetric => NT form); precise ----
    cg(1,1, outRe,outIm, Xr,Xi, Ur,Ui, ROWS,D_MODEL,D_MODEL,
       D_MODEL,D_MODEL,1,D_MODEL, 1.f,0);
}

// round 4
// speedup vs baseline: 3.8666x; 1.4636x over previous
#include <cuda_runtime.h>
#include <cuda_bf16.h>
#include <math.h>
#include <stdint.h>

#define SEQ     1024
#define D_MODEL 1024
#define NHEADS  16
#define DHEAD   64
#define HIDDEN  4096
#define NBATCH  2
#define ROWS    (NBATCH*SEQ)   // 2048

// ---------------- scratch (device statics; no allocation) ----------------
__device__ __align__(128) float g_Qr[ROWS*D_MODEL];
__device__ __align__(128) float g_Qi[ROWS*D_MODEL];
__device__ __align__(128) float g_Kr[ROWS*D_MODEL];
__device__ __align__(128) float g_Ki[ROWS*D_MODEL];
__device__ __align__(128) float g_Vr[ROWS*D_MODEL];
__device__ __align__(128) float g_Vi[ROWS*D_MODEL];
__device__ __align__(128) float g_Xr[ROWS*D_MODEL];
__device__ __align__(128) float g_Xi[ROWS*D_MODEL];
__device__ __align__(128) float g_Or[ROWS*D_MODEL];
__device__ __align__(128) float g_Oi[ROWS*D_MODEL];
__device__ __align__(128) float g_Hr[ROWS*HIDDEN];
__device__ __align__(128) float g_Hi[ROWS*HIDDEN];
__device__ __align__(128) float g_Sc[NBATCH*NHEADS*SEQ*SEQ];
__device__ __align__(128) float g_M [D_MODEL*D_MODEL];
__device__ __align__(128) float g_Ta[D_MODEL*D_MODEL];
__device__ __align__(128) float g_Tb[D_MODEL*D_MODEL];
__device__ __align__(128) float g_Ur[D_MODEL*D_MODEL];
__device__ __align__(128) float g_Ui[D_MODEL*D_MODEL];

// ---------------- low-level helpers ----------------
__device__ __forceinline__ uint32_t f2tf32(float x) {
    uint32_t r;
    asm("cvt.rna.tf32.f32 %0, %1;" : "=r"(r) : "f"(x));
    return r;
}
__device__ __forceinline__ void mma_tf32(float* d, const uint32_t* a, const uint32_t* b) {
    asm volatile(
        "mma.sync.aligned.m16n8k8.row.col.f32.tf32.tf32.f32 "
        "{%0,%1,%2,%3}, {%4,%5,%6,%7}, {%8,%9}, {%0,%1,%2,%3};\n"
        : "+f"(d[0]), "+f"(d[1]), "+f"(d[2]), "+f"(d[3])
        : "r"(a[0]), "r"(a[1]), "r"(a[2]), "r"(a[3]), "r"(b[0]), "r"(b[1]));
}
__device__ __forceinline__ void mma_bf16(float* d, const uint32_t* a, const uint32_t* b) {
    asm volatile(
        "mma.sync.aligned.m16n8k16.row.col.f32.bf16.bf16.f32 "
        "{%0,%1,%2,%3}, {%4,%5,%6,%7}, {%8,%9}, {%0,%1,%2,%3};\n"
        : "+f"(d[0]), "+f"(d[1]), "+f"(d[2]), "+f"(d[3])
        : "r"(a[0]), "r"(a[1]), "r"(a[2]), "r"(a[3]), "r"(b[0]), "r"(b[1]));
}
// pack pair -> bf16x2 word: lower half = bf16(x0), upper = bf16(x1)
__device__ __forceinline__ uint32_t pack_pair(float x0, float x1) {
    uint32_t r;
    asm("cvt.rn.bf16x2.f32 %0, %1, %2;" : "=r"(r) : "f"(x1), "f"(x0));
    return r;
}
__device__ __forceinline__ float gelu_f(float v) {
    return 0.5f * v * (1.0f + erff(v * 0.7071067811865476f));
}

// =================== FAST tf32 GEMM (double-buffered) ===================
// MODE 0: REAL    C  = alpha*(Ar.Br^T)  (+C)
// MODE 1: COMPLEX Cr = Ar.Br^T - Ai.Bi^T (+bias,gelu) (+C); Ci = Ar.Bi^T + Ai.Br^T
// MODE 3: REAL_A  Cr = Ar.Br^T ; Ci = Ar.Bi^T
// A k-contiguous (sAk==1). B: sBk==1 (k-contig) or sBn==1 (n-contig).
// M%128==0, N%64==0, K%32==0.
template<int MODE>
__global__ __launch_bounds__(256, 1) void cgemm_f(
    float* __restrict__ Cr, float* __restrict__ Ci,
    const float* __restrict__ Ar, const float* __restrict__ Ai,
    const float* __restrict__ Br, const float* __restrict__ Bi,
    int M, int N, int K,
    long long sAm, long long sBn, long long sBk, long long sCm,
    long long aB1, long long aB2, long long bB1, long long bB2,
    long long cB1, long long cB2, int batchDiv,
    float alpha, int accumulate,
    const float* __restrict__ biasR, const float* __restrict__ biasI, int gelu)
{
    constexpr bool AC = (MODE == 1);
    constexpr bool BC = (MODE == 1 || MODE == 3);
    constexpr int BM = 128, BN = 64, BK = 32, LDS = 36;
    constexpr int MT = 2, NT = 4;
    constexpr int AT = BM * LDS, BT = BN * LDS;
    constexpr int nA = AC ? 2 : 1, nB = BC ? 2 : 1;
    constexpr int STAGE = nA * AT + nB * BT;

    extern __shared__ uint32_t smem[];

    int z = blockIdx.z, zb = z / batchDiv, zh = z % batchDiv;
    Ar += (long long)zb * aB1 + (long long)zh * aB2;
    if constexpr (AC) Ai += (long long)zb * aB1 + (long long)zh * aB2;
    Br += (long long)zb * bB1 + (long long)zh * bB2;
    if constexpr (BC) Bi += (long long)zb * bB1 + (long long)zh * bB2;
    Cr += (long long)zb * cB1 + (long long)zh * cB2;
    if constexpr (MODE == 1 || MODE == 3) Ci += (long long)zb * cB1 + (long long)zh * cB2;

    int m0 = blockIdx.y * BM, n0 = blockIdx.x * BN;
    int tid = threadIdx.x;
    int lane = tid & 31, w = tid >> 5;
    int mbase = (w >> 1) * 32, nbase = (w & 1) * 32;
    int lg = lane >> 2, lt = lane & 3;

    float accP[MT][NT][4], accI[MT][NT][4];
    #pragma unroll
    for (int mt = 0; mt < MT; mt++)
        #pragma unroll
        for (int nt = 0; nt < NT; nt++)
            #pragma unroll
            for (int e = 0; e < 4; e++) { accP[mt][nt][e] = 0.f; accI[mt][nt][e] = 0.f; }

    float4 pA[nA][4], pB[nB][2];

    auto ldg = [&](int k0) {
        #pragma unroll
        for (int c = 0; c < nA; c++) {
            const float* G = c ? Ai : Ar;
            #pragma unroll
            for (int i = 0; i < 4; i++) {
                int idx = i * 256 + tid;
                int row = idx >> 3, c4 = idx & 7;
                pA[c][i] = *(const float4*)(G + (long long)(m0 + row) * sAm + k0 + c4 * 4);
            }
        }
        if (sBk == 1) {
            #pragma unroll
            for (int c = 0; c < nB; c++) {
                const float* G = c ? Bi : Br;
                #pragma unroll
                for (int i = 0; i < 2; i++) {
                    int idx = i * 256 + tid;
                    int row = idx >> 3, c4 = idx & 7;
                    pB[c][i] = *(const float4*)(G + (long long)(n0 + row) * sBn + k0 + c4 * 4);
                }
            }
        } else {
            #pragma unroll
            for (int c = 0; c < nB; c++) {
                const float* G = c ? Bi : Br;
                #pragma unroll
                for (int i = 0; i < 2; i++) {
                    int idx = i * 256 + tid;
                    int k = idx >> 4, c4 = idx & 15;
                    pB[c][i] = *(const float4*)(G + (long long)(k0 + k) * sBk + n0 + c4 * 4);
                }
            }
        }
    };

    auto sts = [&](uint32_t* base) {
        #pragma unroll
        for (int c = 0; c < nA; c++) {
            uint32_t* SH = base + c * AT;
            #pragma unroll
            for (int i = 0; i < 4; i++) {
                int idx = i * 256 + tid;
                int row = idx >> 3, c4 = idx & 7;
                float4 v = pA[c][i];
                uint32_t* p = SH + row * LDS + c4 * 4;
                p[0] = f2tf32(v.x); p[1] = f2tf32(v.y);
                p[2] = f2tf32(v.z); p[3] = f2tf32(v.w);
            }
        }
        if (sBk == 1) {
            #pragma unroll
            for (int c = 0; c < nB; c++) {
                uint32_t* SH = base + nA * AT + c * BT;
                #pragma unroll
                for (int i = 0; i < 2; i++) {
                    int idx = i * 256 + tid;
                    int row = idx >> 3, c4 = idx & 7;
                    float4 v = pB[c][i];
                    uint32_t* p = SH + row * LDS + c4 * 4;
                    p[0] = f2tf32(v.x); p[1] = f2tf32(v.y);
                    p[2] = f2tf32(v.z); p[3] = f2tf32(v.w);
                }
            }
        } else {
            #pragma unroll
            for (int c = 0; c < nB; c++) {
                uint32_t* SH = base + nA * AT + c * BT;
                #pragma unroll
                for (int i = 0; i < 2; i++) {
                    int idx = i * 256 + tid;
                    int k = idx >> 4, c4 = idx & 15;
                    float4 v = pB[c][i];
                    float xs[4] = { v.x, v.y, v.z, v.w };
                    #pragma unroll
                    for (int j = 0; j < 4; j++)
                        SH[(c4 * 4 + j) * LDS + k] = f2tf32(xs[j]);
                }
            }
        }
    };

    auto compute = [&](uint32_t* base) {
        const uint32_t* sAr = base;
        const uint32_t* sAi = base + AT;
        const uint32_t* sBr = base + nA * AT;
        const uint32_t* sBi = sBr + BT;
        #pragma unroll
        for (int kk = 0; kk < BK; kk += 8) {
            uint32_t ar[MT][4], ai[MT][4];
            uint32_t br[NT][2], bi[NT][2];
            #pragma unroll
            for (int mt = 0; mt < MT; mt++) {
                int o0 = (mbase + mt * 16 + lg) * LDS + kk + lt;
                int o1 = o0 + 8 * LDS;
                ar[mt][0] = sAr[o0];   ar[mt][1] = sAr[o1];
                ar[mt][2] = sAr[o0+4]; ar[mt][3] = sAr[o1+4];
                if constexpr (AC) {
                    ai[mt][0] = sAi[o0];   ai[mt][1] = sAi[o1];
                    ai[mt][2] = sAi[o0+4]; ai[mt][3] = sAi[o1+4];
                }
            }
            #pragma unroll
            for (int nt = 0; nt < NT; nt++) {
                int o0 = (nbase + nt * 8 + lg) * LDS + kk + lt;
                br[nt][0] = sBr[o0]; br[nt][1] = sBr[o0+4];
                if constexpr (BC) { bi[nt][0] = sBi[o0]; bi[nt][1] = sBi[o0+4]; }
            }
            #pragma unroll
            for (int nt = 0; nt < NT; nt++) {
                uint32_t nbi[2];
                if constexpr (MODE == 1) {
                    nbi[0] = bi[nt][0] ^ 0x80000000u;
                    nbi[1] = bi[nt][1] ^ 0x80000000u;
                }
                #pragma unroll
                for (int mt = 0; mt < MT; mt++) {
                    if constexpr (MODE == 0) {
                        mma_tf32(accP[mt][nt], ar[mt], br[nt]);
                    } else if constexpr (MODE == 1) {
                        mma_tf32(accP[mt][nt], ar[mt], br[nt]);
                        mma_tf32(accP[mt][nt], ai[mt], nbi);
                        mma_tf32(accI[mt][nt], ar[mt], bi[nt]);
                        mma_tf32(accI[mt][nt], ai[mt], br[nt]);
                    } else {
                        mma_tf32(accP[mt][nt], ar[mt], br[nt]);
                        mma_tf32(accI[mt][nt], ar[mt], bi[nt]);
                    }
                }
            }
        }
    };

    uint32_t* cur = smem;
    uint32_t* nxt = smem + STAGE;
    ldg(0);
    sts(cur);
    __syncthreads();
    for (int k0 = 0;;) {
        int kn = k0 + BK;
        bool more = kn < K;
        if (more) ldg(kn);
        compute(cur);
        if (!more) break;
        sts(nxt);
        __syncthreads();
        uint32_t* t = cur; cur = nxt; nxt = t;
        k0 = kn;
    }

    // ---- epilogue ----
    #pragma unroll
    for (int mt = 0; mt < MT; mt++)
        #pragma unroll
        for (int nt = 0; nt < NT; nt++)
            #pragma unroll
            for (int e = 0; e < 4; e++) {
                int gm = m0 + mbase + mt * 16 + lg + (e >> 1) * 8;
                int gn = n0 + nbase + nt * 8 + lt * 2 + (e & 1);
                long long p = (long long)gm * sCm + gn;
                if constexpr (MODE == 1) {
                    float vr = accP[mt][nt][e];
                    float vi = accI[mt][nt][e];
                    if (biasR) { vr += biasR[gn]; vi += biasI[gn]; }
                    if (gelu)  { vr = gelu_f(vr); vi = gelu_f(vi); }
                    if (accumulate) { vr += Cr[p]; vi += Ci[p]; }
                    Cr[p] = vr; Ci[p] = vi;
                } else if constexpr (MODE == 3) {
                    Cr[p] = accP[mt][nt][e];
                    Ci[p] = accI[mt][nt][e];
                } else {
                    float v = alpha * accP[mt][nt][e];
                    if (accumulate) v += Cr[p];
                    Cr[p] = v;
                }
            }
}

// =================== PRECISE split-bf16 GEMM (double-buffered) ===================
// fp32 = bf16_hi + bf16_lo; D += AhBh + AhBl + AlBh  (error ~2^-17 per product)
// MODE 1: COMPLEX  Cr = Ar.Br^T - Ai.Bi^T (+bias) (+C); Ci = Ar.Bi^T + Ai.Br^T
// MODE 2: CONJ_REAL C = alpha*(Ar.Br^T + Ai.Bi^T) (+C)
// Both A and B k-contiguous. M%128==0, N%64==0, K%32==0.
template<int MODE>
__global__ __launch_bounds__(256, 1) void cgemm_p(
    float* __restrict__ Cr, float* __restrict__ Ci,
    const float* __restrict__ Ar, const float* __restrict__ Ai,
    const float* __restrict__ Br, const float* __restrict__ Bi,
    int M, int N, int K,
    long long sAm, long long sBn, long long sBk, long long sCm,
    long long aB1, long long aB2, long long bB1, long long bB2,
    long long cB1, long long cB2, int batchDiv,
    float alpha, int accumulate,
    const float* __restrict__ biasR, const float* __restrict__ biasI, int gelu)
{
    constexpr int BM = 128, BN = 64, BK = 32, LDB = 20;   // packed words/row: 16 + pad 4
    constexpr int MT = 2, NT = 4;
    constexpr int APW = BM * LDB;       // words per A plane
    constexpr int BPW = BN * LDB;
    constexpr int STAGE = 4 * APW + 4 * BPW;   // ArH,ArL,AiH,AiL,BrH,BrL,BiH,BiL

    extern __shared__ uint32_t smem[];

    int z = blockIdx.z, zb = z / batchDiv, zh = z % batchDiv;
    Ar += (long long)zb * aB1 + (long long)zh * aB2;
    Ai += (long long)zb * aB1 + (long long)zh * aB2;
    Br += (long long)zb * bB1 + (long long)zh * bB2;
    Bi += (long long)zb * bB1 + (long long)zh * bB2;
    Cr += (long long)zb * cB1 + (long long)zh * cB2;
    if constexpr (MODE == 1) Ci += (long long)zb * cB1 + (long long)zh * cB2;

    int m0 = blockIdx.y * BM, n0 = blockIdx.x * BN;
    int tid = threadIdx.x;
    int lane = tid & 31, w = tid >> 5;
    int mbase = (w >> 1) * 32, nbase = (w & 1) * 32;
    int lg = lane >> 2, lt = lane & 3;

    float accP[MT][NT][4], accI[MT][NT][4];
    #pragma unroll
    for (int mt = 0; mt < MT; mt++)
        #pragma unroll
        for (int nt = 0; nt < NT; nt++)
            #pragma unroll
            for (int e = 0; e < 4; e++) { accP[mt][nt][e] = 0.f; accI[mt][nt][e] = 0.f; }

    float4 pA[2][4], pB[2][2];

    auto ldg = [&](int k0) {
        #pragma unroll
        for (int c = 0; c < 2; c++) {
            const float* G = c ? Ai : Ar;
            #pragma unroll
            for (int i = 0; i < 4; i++) {
                int idx = i * 256 + tid;
                int row = idx >> 3, c4 = idx & 7;
                pA[c][i] = *(const float4*)(G + (long long)(m0 + row) * sAm + k0 + c4 * 4);
            }
        }
        #pragma unroll
        for (int c = 0; c < 2; c++) {
            const float* G = c ? Bi : Br;
            #pragma unroll
            for (int i = 0; i < 2; i++) {
                int idx = i * 256 + tid;
                int row = idx >> 3, c4 = idx & 7;
                pB[c][i] = *(const float4*)(G + (long long)(n0 + row) * sBn + k0 + c4 * 4);
            }
        }
    };

    auto split_store = [&](float4 v, uint32_t* hiP, uint32_t* loP) {
        uint32_t h0 = pack_pair(v.x, v.y);
        uint32_t h1 = pack_pair(v.z, v.w);
        float fx = __uint_as_float(h0 << 16);
        float fy = __uint_as_float(h0 & 0xFFFF0000u);
        float fz = __uint_as_float(h1 << 16);
        float fw = __uint_as_float(h1 & 0xFFFF0000u);
        uint32_t l0 = pack_pair(v.x - fx, v.y - fy);
        uint32_t l1 = pack_pair(v.z - fz, v.w - fw);
        hiP[0] = h0; hiP[1] = h1;
        loP[0] = l0; loP[1] = l1;
    };

    auto sts = [&](uint32_t* base) {
        #pragma unroll
        for (int c = 0; c < 2; c++) {
            uint32_t* SH = base + c * 2 * APW;     // hi plane; lo at +APW
            #pragma unroll
            for (int i = 0; i < 4; i++) {
                int idx = i * 256 + tid;
                int row = idx >> 3, c4 = idx & 7;
                uint32_t* p = SH + row * LDB + c4 * 2;
                split_store(pA[c][i], p, p + APW);
            }
        }
        #pragma unroll
        for (int c = 0; c < 2; c++) {
            uint32_t* SH = base + 4 * APW + c * 2 * BPW;
            #pragma unroll
            for (int i = 0; i < 2; i++) {
                int idx = i * 256 + tid;
                int row = idx >> 3, c4 = idx & 7;
                uint32_t* p = SH + row * LDB + c4 * 2;
                split_store(pB[c][i], p, p + BPW);
            }
        }
    };

    auto compute = [&](uint32_t* base) {
        const uint32_t* sArH = base;
        const uint32_t* sAiH = base + 2 * APW;
        const uint32_t* sBrH = base + 4 * APW;
        const uint32_t* sBiH = sBrH + 2 * BPW;
        #pragma unroll
        for (int kk = 0; kk < 16; kk += 8) {     // two k16 chunks per BK=32
            uint32_t arH[MT][4], arL[MT][4], aiH[MT][4], aiL[MT][4];
            uint32_t brH[NT][2], brL[NT][2], biH[NT][2], biL[NT][2];
            #pragma unroll
            for (int mt = 0; mt < MT; mt++) {
                int o0 = (mbase + mt * 16 + lg) * LDB + kk + lt;
                int o1 = o0 + 8 * LDB;
                arH[mt][0] = sArH[o0];     arH[mt][1] = sArH[o1];
                arH[mt][2] = sArH[o0+4];   arH[mt][3] = sArH[o1+4];
                arL[mt][0] = sArH[o0+APW];   arL[mt][1] = sArH[o1+APW];
                arL[mt][2] = sArH[o0+4+APW]; arL[mt][3] = sArH[o1+4+APW];
                aiH[mt][0] = sAiH[o0];     aiH[mt][1] = sAiH[o1];
                aiH[mt][2] = sAiH[o0+4];   aiH[mt][3] = sAiH[o1+4];
                aiL[mt][0] = sAiH[o0+APW];   aiL[mt][1] = sAiH[o1+APW];
                aiL[mt][2] = sAiH[o0+4+APW]; aiL[mt][3] = sAiH[o1+4+APW];
            }
            #pragma unroll
            for (int nt = 0; nt < NT; nt++) {
                int o0 = (nbase + nt * 8 + lg) * LDB + kk + lt;
                brH[nt][0] = sBrH[o0];     brH[nt][1] = sBrH[o0+4];
                brL[nt][0] = sBrH[o0+BPW]; brL[nt][1] = sBrH[o0+4+BPW];
                biH[nt][0] = sBiH[o0];     biH[nt][1] = sBiH[o0+4];
                biL[nt][0] = sBiH[o0+BPW]; biL[nt][1] = sBiH[o0+4+BPW];
            }
            #pragma unroll
            for (int nt = 0; nt < NT; nt++) {
                uint32_t nbiH[2], nbiL[2];
                if constexpr (MODE == 1) {
                    nbiH[0] = biH[nt][0] ^ 0x80008000u; nbiH[1] = biH[nt][1] ^ 0x80008000u;
                    nbiL[0] = biL[nt][0] ^ 0x80008000u; nbiL[1] = biL[nt][1] ^ 0x80008000u;
                }
                #pragma unroll
                for (int mt = 0; mt < MT; mt++) {
                    if constexpr (MODE == 1) {
                        mma_bf16(accP[mt][nt], arH[mt], brH[nt]);
                        mma_bf16(accP[mt][nt], arH[mt], brL[nt]);
                        mma_bf16(accP[mt][nt], arL[mt], brH[nt]);
                        mma_bf16(accP[mt][nt], aiH[mt], nbiH);
                        mma_bf16(accP[mt][nt], aiH[mt], nbiL);
                        mma_bf16(accP[mt][nt], aiL[mt], nbiH);
                        mma_bf16(accI[mt][nt], arH[mt], biH[nt]);
                        mma_bf16(accI[mt][nt], arH[mt], biL[nt]);
                        mma_bf16(accI[mt][nt], arL[mt], biH[nt]);
                        mma_bf16(accI[mt][nt], aiH[mt], brH[nt]);
                        mma_bf16(accI[mt][nt], aiH[mt], brL[nt]);
                        mma_bf16(accI[mt][nt], aiL[mt], brH[nt]);
                    } else {
                        mma_bf16(accP[mt][nt], arH[mt], brH[nt]);
                        mma_bf16(accP[mt][nt], arH[mt], brL[nt]);
                        mma_bf16(accP[mt][nt], arL[mt], brH[nt]);
                        mma_bf16(accP[mt][nt], aiH[mt], biH[nt]);
                        mma_bf16(accP[mt][nt], aiH[mt], biL[nt]);
                        mma_bf16(accP[mt][nt], aiL[mt], biH[nt]);
                    }
                }
            }
        }
    };

    uint32_t* cur = smem;
    uint32_t* nxt = smem + STAGE;
    ldg(0);
    sts(cur);
    __syncthreads();
    for (int k0 = 0;;) {
        int kn = k0 + BK;
        bool more = kn < K;
        if (more) ldg(kn);
        compute(cur);
        if (!more) break;
        sts(nxt);
        __syncthreads();
        uint32_t* t = cur; cur = nxt; nxt = t;
        k0 = kn;
    }

    // ---- epilogue ----
    #pragma unroll
    for (int mt = 0; mt < MT; mt++)
        #pragma unroll
        for (int nt = 0; nt < NT; nt++)
            #pragma unroll
            for (int e = 0; e < 4; e++) {
                int gm = m0 + mbase + mt * 16 + lg + (e >> 1) * 8;
                int gn = n0 + nbase + nt * 8 + lt * 2 + (e & 1);
                long long p = (long long)gm * sCm + gn;
                if constexpr (MODE == 1) {
                    float vr = accP[mt][nt][e];
                    float vi = accI[mt][nt][e];
                    if (biasR) { vr += biasR[gn]; vi += biasI[gn]; }
                    if (gelu)  { vr = gelu_f(vr); vi = gelu_f(vi); }
                    if (accumulate) { vr += Cr[p]; vi += Ci[p]; }
                    Cr[p] = vr; Ci[p] = vi;
                } else {
                    float v = alpha * accP[mt][nt][e];
                    if (accumulate) v += Cr[p];
                    Cr[p] = v;
                }
            }
}

// ---------------- 1024-pt complex FFT (radix-2 Stockham) ----------------
__global__ __launch_bounds__(512) void fft_kernel(float* __restrict__ re,
                                                  float* __restrict__ im,
                                                  int inverse)
{
    __shared__ float sr[2][1024];
    __shared__ float si[2][1024];
    int col = blockIdx.x;
    int b   = col >> 10;
    int rem = col & 1023;
    long long base = (long long)b * SEQ * D_MODEL + rem;
    int t = threadIdx.x;

    sr[0][t]      = re[base + (long long)t*D_MODEL];
    si[0][t]      = im[base + (long long)t*D_MODEL];
    sr[0][t+512]  = re[base + (long long)(t+512)*D_MODEL];
    si[0][t+512]  = im[base + (long long)(t+512)*D_MODEL];
    __syncthreads();

    float sgn = inverse ? 6.283185307179586f : -6.283185307179586f;
    int cur = 0;
    #pragma unroll
    for (int s = 0; s < 10; s++) {
        int L = 1 << s;
        int l = t & (L-1);
        int r = t >> s;
        float ar = sr[cur][t],     ai = si[cur][t];
        float br = sr[cur][t+512], bi = si[cur][t+512];
        float ang = sgn * (float)l / (float)(2*L);
        float c, sn;
        sincosf(ang, &sn, &c);
        float tr = c*br - sn*bi;
        float ti = c*bi + sn*br;
        int nxt = cur ^ 1;
        int o = r*(2*L) + l;
        sr[nxt][o]   = ar + tr;  si[nxt][o]   = ai + ti;
        sr[nxt][o+L] = ar - tr;  si[nxt][o+L] = ai - ti;
        cur = nxt;
        __syncthreads();
    }
    float sc = inverse ? (1.0f/1024.0f) : 1.0f;
    re[base + (long long)t*D_MODEL]       = sr[cur][t]*sc;
    im[base + (long long)t*D_MODEL]       = si[cur][t]*sc;
    re[base + (long long)(t+512)*D_MODEL] = sr[cur][t+512]*sc;
    im[base + (long long)(t+512)*D_MODEL] = si[cur][t+512]*sc;
}

// ---------------- row softmax over 1024 columns ----------------
__global__ __launch_bounds__(256) void softmax_kernel(float* __restrict__ S)
{
    long long row = blockIdx.x;
    float* p = S + row*1024;
    int t = threadIdx.x;
    __shared__ float red[256];

    float m = -1e30f;
    #pragma unroll
    for (int i = 0; i < 4; i++) m = fmaxf(m, p[t + i*256]);
    red[t] = m; __syncthreads();
    for (int s = 128; s > 0; s >>= 1) { if (t < s) red[t] = fmaxf(red[t], red[t+s]); __syncthreads(); }
    m = red[0]; __syncthreads();

    float vals[4]; float sum = 0.f;
    #pragma unroll
    for (int i = 0; i < 4; i++) { vals[i] = expf(p[t + i*256] - m); sum += vals[i]; }
    red[t] = sum; __syncthreads();
    for (int s = 128; s > 0; s >>= 1) { if (t < s) red[t] += red[t+s]; __syncthreads(); }
    float inv = 1.0f / red[0];
    #pragma unroll
    for (int i = 0; i < 4; i++) p[t + i*256] = vals[i]*inv;
}

// ---------------- elementwise helpers ----------------
__global__ void copy_kernel(float* __restrict__ y, const float* __restrict__ x, long long n)
{
    long long i = (long long)blockIdx.x*blockDim.x + threadIdx.x;
    if (i < n) y[i] = x[i];
}
__global__ void scale_kernel(float* __restrict__ y, const float* __restrict__ x,
                             const float* __restrict__ dt, long long n)
{
    long long i = (long long)blockIdx.x*blockDim.x + threadIdx.x;
    if (i < n) y[i] = x[i]*dt[0];
}
__global__ void initU_kernel(float* __restrict__ Ur, float* __restrict__ Ui)
{
    long long i = (long long)blockIdx.x*blockDim.x + threadIdx.x;
    if (i < (long long)D_MODEL*D_MODEL) {
        Ur[i] = ((i / D_MODEL) == (i % D_MODEL)) ? 1.f : 0.f;
        Ui[i] = 0.f;
    }
}
__global__ void axpy_kernel(float* __restrict__ y, const float* __restrict__ x,
                            float c, long long n)
{
    long long i = (long long)blockIdx.x*blockDim.x + threadIdx.x;
    if (i < n) y[i] += c*x[i];
}

// ---------------- host orchestration ----------------
static void cgf(int mode,
    float* Cr, float* Ci,
    const float* Ar, const float* Ai,
    const float* Br, const float* Bi,
    int M, int N, int K,
    long long sAm, long long sBn, long long sBk, long long sCm,
    float alpha, int acc,
    const float* bR = nullptr, const float* bI = nullptr, int gelu = 0,
    int batch = 1, int batchDiv = 1,
    long long aB1 = 0, long long aB2 = 0,
    long long bB1 = 0, long long bB2 = 0,
    long long cB1 = 0, long long cB2 = 0)
{
    dim3 grid(N / 64, M / 128, batch);
    int nA = (mode == 1) ? 2 : 1;
    int nB = (mode == 0) ? 1 : 2;
    size_t sh = (size_t)(nA * 128 + nB * 64) * 36 * 4 * 2;
    #define ARGS Cr, Ci, Ar, Ai, Br, Bi, M, N, K, sAm, sBn, sBk, sCm, \
                 aB1, aB2, bB1, bB2, cB1, cB2, batchDiv, alpha, acc, bR, bI, gelu
    if      (mode == 1) cgemm_f<1><<<grid, 256, sh>>>(ARGS);
    else if (mode == 3) cgemm_f<3><<<grid, 256, sh>>>(ARGS);
    else                cgemm_f<0><<<grid, 256, sh>>>(ARGS);
    #undef ARGS
}

static void cgp(int mode,
    float* Cr, float* Ci,
    const float* Ar, const float* Ai,
    const float* Br, const float* Bi,
    int M, int N, int K,
    long long sAm, long long sBn, long long sBk, long long sCm,
    float alpha, int acc,
    const float* bR = nullptr, const float* bI = nullptr, int gelu = 0,
    int batch = 1, int batchDiv = 1,
    long long aB1 = 0, long long aB2 = 0,
    long long bB1 = 0, long long bB2 = 0,
    long long cB1 = 0, long long cB2 = 0)
{
    dim3 grid(N / 64, M / 128, batch);
    size_t sh = (size_t)(4 * 128 * 20 + 4 * 64 * 20) * 4 * 2;   // 122880
    #define ARGS Cr, Ci, Ar, Ai, Br, Bi, M, N, K, sAm, sBn, sBk, sCm, \
                 aB1, aB2, bB1, bB2, cB1, cB2, batchDiv, alpha, acc, bR, bI, gelu
    if (mode == 1) cgemm_p<1><<<grid, 256, sh>>>(ARGS);
    else           cgemm_p<2><<<grid, 256, sh>>>(ARGS);
    #undef ARGS
}

extern "C" void kernel_launch(void* const* d_in, const int* in_sizes, int n_in,
                              void* d_out, int out_size)
{
    cudaFuncSetAttribute(cgemm_f<1>, cudaFuncAttributeMaxDynamicSharedMemorySize, 110592);
    cudaFuncSetAttribute(cgemm_f<3>, cudaFuncAttributeMaxDynamicSharedMemorySize, 73728);
    cudaFuncSetAttribute(cgemm_f<0>, cudaFuncAttributeMaxDynamicSharedMemorySize, 55296);
    cudaFuncSetAttribute(cgemm_p<1>, cudaFuncAttributeMaxDynamicSharedMemorySize, 122880);
    cudaFuncSetAttribute(cgemm_p<2>, cudaFuncAttributeMaxDynamicSharedMemorySize, 122880);

    const float* x_real = (const float*)d_in[0];
    const float* x_imag = (const float*)d_in[1];
    const float* Wr_q = (const float*)d_in[2];   const float* Wi_q = (const float*)d_in[3];
    const float* br_q = (const float*)d_in[4];   const float* bi_q = (const float*)d_in[5];
    const float* Wr_k = (const float*)d_in[6];   const float* Wi_k = (const float*)d_in[7];
    const float* br_k = (const float*)d_in[8];   const float* bi_k = (const float*)d_in[9];
    const float* Wr_v = (const float*)d_in[10];  const float* Wi_v = (const float*)d_in[11];
    const float* br_v = (const float*)d_in[12];  const float* bi_v = (const float*)d_in[13];
    const float* Wr_o = (const float*)d_in[14];  const float* Wi_o = (const float*)d_in[15];
    const float* br_o = (const float*)d_in[16];  const float* bi_o = (const float*)d_in[17];
    const float* Wr_f1 = (const float*)d_in[18]; const float* Wi_f1 = (const float*)d_in[19];
    const float* br_f1 = (const float*)d_in[20]; const float* bi_f1 = (const float*)d_in[21];
    const float* Wr_f2 = (const float*)d_in[22]; const float* Wi_f2 = (const float*)d_in[23];
    const float* br_f2 = (const float*)d_in[24]; const float* bi_f2 = (const float*)d_in[25];
    const float* Hmat = (const float*)d_in[26];
    const float* dtp  = (const float*)d_in[27];

    float* outRe = (float*)d_out;
    float* outIm = outRe + (long long)ROWS*D_MODEL;

    float *Qr,*Qi,*Kr,*Ki,*Vr,*Vi,*Xr,*Xi,*Or,*Oi,*Hr,*Hi,*Sc,*Mb,*Ta,*Tb,*Ur,*Ui;
    cudaGetSymbolAddress((void**)&Qr, g_Qr); cudaGetSymbolAddress((void**)&Qi, g_Qi);
    cudaGetSymbolAddress((void**)&Kr, g_Kr); cudaGetSymbolAddress((void**)&Ki, g_Ki);
    cudaGetSymbolAddress((void**)&Vr, g_Vr); cudaGetSymbolAddress((void**)&Vi, g_Vi);
    cudaGetSymbolAddress((void**)&Xr, g_Xr); cudaGetSymbolAddress((void**)&Xi, g_Xi);
    cudaGetSymbolAddress((void**)&Or, g_Or); cudaGetSymbolAddress((void**)&Oi, g_Oi);
    cudaGetSymbolAddress((void**)&Hr, g_Hr); cudaGetSymbolAddress((void**)&Hi, g_Hi);
    cudaGetSymbolAddress((void**)&Sc, g_Sc);
    cudaGetSymbolAddress((void**)&Mb, g_M);  cudaGetSymbolAddress((void**)&Ta, g_Ta);
    cudaGetSymbolAddress((void**)&Tb, g_Tb);
    cudaGetSymbolAddress((void**)&Ur, g_Ur); cudaGetSymbolAddress((void**)&Ui, g_Ui);

    const long long ND = (long long)ROWS*D_MODEL;
    const long long DD = (long long)D_MODEL*D_MODEL;
    const long long hM = (long long)SEQ*SEQ;
    copy_kernel<<<(int)((ND+255)/256), 256>>>(Xr, x_real, ND);
    copy_kernel<<<(int)((ND+255)/256), 256>>>(Xi, x_imag, ND);

    // ---- Q/K/V projections (Q/K precise for softmax logit sensitivity) ----
    cgp(1, Qr,Qi, Xr,Xi, Wr_q,Wi_q, ROWS,D_MODEL,D_MODEL, D_MODEL,D_MODEL,1,D_MODEL, 1.f,0, br_q,bi_q,0);
    cgp(1, Kr,Ki, Xr,Xi, Wr_k,Wi_k, ROWS,D_MODEL,D_MODEL, D_MODEL,D_MODEL,1,D_MODEL, 1.f,0, br_k,bi_k,0);
    cgf(1, Vr,Vi, Xr,Xi, Wr_v,Wi_v, ROWS,D_MODEL,D_MODEL, D_MODEL,D_MODEL,1,D_MODEL, 1.f,0, br_v,bi_v,0);

    // ---- forward FFT along sequence axis ----
    fft_kernel<<<NBATCH*D_MODEL, 512>>>(Qr, Qi, 0);
    fft_kernel<<<NBATCH*D_MODEL, 512>>>(Kr, Ki, 0);
    fft_kernel<<<NBATCH*D_MODEL, 512>>>(Vr, Vi, 0);

    // ---- scores = scale*Re(Qf conj(Kf)); precise ----
    cgp(2, Sc,nullptr, Qr,Qi, Kr,Ki, SEQ,SEQ,DHEAD,
        D_MODEL,D_MODEL,1,SEQ, 0.125f,0, nullptr,nullptr,0,
        NBATCH*NHEADS, NHEADS,
        (long long)SEQ*D_MODEL, DHEAD,
        (long long)SEQ*D_MODEL, DHEAD,
        (long long)NHEADS*hM, hM);

    softmax_kernel<<<NBATCH*NHEADS*SEQ, 256>>>(Sc);

    // ---- out_f = attn @ Vf (attn real, V complex, B n-contiguous) ----
    cgf(3, Or,Oi, Sc,nullptr, Vr,Vi, SEQ,DHEAD,SEQ,
        SEQ,1,D_MODEL,D_MODEL, 1.f,0, nullptr,nullptr,0,
        NBATCH*NHEADS, NHEADS,
        (long long)NHEADS*hM, hM,
        (long long)SEQ*D_MODEL, DHEAD,
        (long long)SEQ*D_MODEL, DHEAD);

    // ---- inverse FFT ----
    fft_kernel<<<NBATCH*D_MODEL, 512>>>(Or, Oi, 1);

    // ---- x += clin(out, Wo) ----
    cgf(1, Xr,Xi, Or,Oi, Wr_o,Wi_o, ROWS,D_MODEL,D_MODEL, D_MODEL,D_MODEL,1,D_MODEL, 1.f,1, br_o,bi_o,0);

    // ---- FFN ----
    cgf(1, Hr,Hi, Xr,Xi, Wr_f1,Wi_f1, ROWS,HIDDEN,D_MODEL, D_MODEL,D_MODEL,1,HIDDEN, 1.f,0, br_f1,bi_f1,1);
    cgf(1, Xr,Xi, Hr,Hi, Wr_f2,Wi_f2, ROWS,D_MODEL,HIDDEN, HIDDEN,HIDDEN,1,D_MODEL, 1.f,1, br_f2,bi_f2,0);

    // ---- U = expm(-i H dt) via Taylor (||H dt||~0.05) ----
    scale_kernel<<<(int)((DD+255)/256), 256>>>(Mb, Hmat, dtp, DD);
    initU_kernel<<<(int)((DD+255)/256), 256>>>(Ur, Ui);
    axpy_kernel<<<(int)((DD+255)/256), 256>>>(Ui, Mb, -1.0f, DD);
    {
        float* prev = Mb;
        float* bufs[2] = { Ta, Tb };
        const int   tgt [5] = { 0, 1, 0, 1, 0 };
        const float coef[5] = { -0.5f, 1.0f/6.0f, 1.0f/24.0f, -1.0f/120.0f, -1.0f/720.0f };
        for (int s = 0; s < 5; s++) {
            float* dst = bufs[s & 1];
            cgf(0, dst,nullptr, prev,nullptr, Mb,nullptr,
                D_MODEL,D_MODEL,D_MODEL, D_MODEL,D_MODEL,1,D_MODEL, 1.f,0);
            axpy_kernel<<<(int)((DD+255)/256), 256>>>(tgt[s] ? Ui : Ur, dst, coef[s], DD);
            prev = dst;
        }
    }

    // ---- out = x @ U (U symmetric => NT form); precise ----
    cgp(1, outRe,outIm, Xr,Xi, Ur,Ui, ROWS,D_MODEL,D_MODEL,
        D_MODEL,D_MODEL,1,D_MODEL, 1.f,0);
}